// round 1
// baseline (speedup 1.0000x reference)
#include <cuda_runtime.h>
#include <math.h>
#include <stdint.h>

#define NP 4096
#define NB 64
#define NC 512
#define NA 256
#define NSPLIT 16

// Scratch (no device allocation allowed)
__device__ float g_t2[NB * NA];                 // attn2 + Wa_b + Ua_b folded
__device__ float g_scores[NP * NB];             // pre-softmax scores
__device__ float g_part[NSPLIT * NB * NC];      // context partials

__device__ __forceinline__ float tf32_rnd(float x) {
    uint32_t u;
    asm("cvt.rna.tf32.f32 %0, %1;" : "=r"(u) : "f"(x));
    return __uint_as_float(u);
}

__device__ __forceinline__ void mma_tf32(float c[4], const float a[4], float b0, float b1) {
    asm volatile(
        "mma.sync.aligned.m16n8k8.row.col.f32.tf32.tf32.f32 "
        "{%0,%1,%2,%3}, {%4,%5,%6,%7}, {%8,%9}, {%0,%1,%2,%3};\n"
        : "+f"(c[0]), "+f"(c[1]), "+f"(c[2]), "+f"(c[3])
        : "r"(__float_as_uint(a[0])), "r"(__float_as_uint(a[1])),
          "r"(__float_as_uint(a[2])), "r"(__float_as_uint(a[3])),
          "r"(__float_as_uint(b0)), "r"(__float_as_uint(b1)));
}

// ---------------------------------------------------------------------------
// Kernel A: t2[b][a] = Ua_w[a,:] . queries[b,:] + Ua_b[a] + Wa_b[a]
// ---------------------------------------------------------------------------
__global__ __launch_bounds__(NA) void attn2_kernel(
    const float* __restrict__ queries, const float* __restrict__ Ua_w,
    const float* __restrict__ Ua_b, const float* __restrict__ Wa_b) {
    __shared__ float qs[NC];
    const int b = blockIdx.x;
    for (int i = threadIdx.x; i < NC; i += blockDim.x) qs[i] = queries[b * NC + i];
    __syncthreads();
    const int a = threadIdx.x;
    const float* ua = Ua_w + (size_t)a * NC;
    float s = 0.f;
#pragma unroll 8
    for (int h = 0; h < NC; h++) s += ua[h] * qs[h];
    g_t2[b * NA + a] = s + Ua_b[a] + Wa_b[a];
}

// ---------------------------------------------------------------------------
// Kernel B: scores[p*64+b] = va . tanh(keys[p,b,:] @ Wa_w^T + t2[b,:]) + va_b
// TF32 mma.sync GEMM, CTA = 64 rows (one p, all b) x 256 cols, K=512.
// 8 warps as 2(m) x 4(n): each warp 32 rows x 64 cols.
// ---------------------------------------------------------------------------
__global__ __launch_bounds__(256, 2) void score_kernel(
    const float* __restrict__ keys, const float* __restrict__ Wa_w,
    const float* __restrict__ va_w, const float* __restrict__ va_b) {
    __shared__ float As[64][20];   // keys tile [row][k], stride 20 (conflict-free frag loads)
    __shared__ float Bs[NA][20];   // Wa tile [n][k]
    __shared__ float red[4][64];
    __shared__ float va_s[NA];

    const int tid = threadIdx.x;
    const int warp = tid >> 5, lane = tid & 31;
    const int wm = warp >> 2, wn = warp & 3;   // wm in {0,1}, wn in {0..3}
    const int gp = lane >> 2, tg = lane & 3;
    const int m0 = blockIdx.x * 64;

    va_s[tid] = va_w[tid];  // blockDim == 256 == NA

    float acc[2][8][4];
#pragma unroll
    for (int i = 0; i < 2; i++)
#pragma unroll
        for (int j = 0; j < 8; j++)
#pragma unroll
            for (int k = 0; k < 4; k++) acc[i][j][k] = 0.f;

    const int lrow = tid >> 2, lq = tid & 3;

    for (int k0 = 0; k0 < NC; k0 += 16) {
        __syncthreads();
        {
            float4 v = *(const float4*)(keys + (size_t)(m0 + lrow) * NC + k0 + lq * 4);
            float* d = &As[lrow][lq * 4];
            d[0] = tf32_rnd(v.x); d[1] = tf32_rnd(v.y);
            d[2] = tf32_rnd(v.z); d[3] = tf32_rnd(v.w);
        }
#pragma unroll
        for (int i = 0; i < 4; i++) {
            int idx = tid + i * 256;
            int row = idx >> 2, q = idx & 3;
            float4 v = *(const float4*)(Wa_w + (size_t)row * NC + k0 + q * 4);
            float* d = &Bs[row][q * 4];
            d[0] = tf32_rnd(v.x); d[1] = tf32_rnd(v.y);
            d[2] = tf32_rnd(v.z); d[3] = tf32_rnd(v.w);
        }
        __syncthreads();
#pragma unroll
        for (int ks = 0; ks < 16; ks += 8) {
            float a[2][4];
#pragma unroll
            for (int mt = 0; mt < 2; mt++) {
                int r0 = wm * 32 + mt * 16;
                a[mt][0] = As[r0 + gp][ks + tg];
                a[mt][1] = As[r0 + gp + 8][ks + tg];
                a[mt][2] = As[r0 + gp][ks + tg + 4];
                a[mt][3] = As[r0 + gp + 8][ks + tg + 4];
            }
#pragma unroll
            for (int nt = 0; nt < 8; nt++) {
                int n0 = wn * 64 + nt * 8;
                float b0 = Bs[n0 + gp][ks + tg];
                float b1 = Bs[n0 + gp][ks + tg + 4];
                mma_tf32(acc[0][nt], a[0], b0, b1);
                mma_tf32(acc[1][nt], a[1], b0, b1);
            }
        }
    }

    // Epilogue: val = tanh(acc + t2[b][n]) * va[n], reduce over n per row.
    float rs00 = 0.f, rs01 = 0.f, rs10 = 0.f, rs11 = 0.f;
#pragma unroll
    for (int mt = 0; mt < 2; mt++) {
        int r0 = wm * 32 + mt * 16 + gp;   // local row == b (tile covers one p)
        int r1 = r0 + 8;
        const float* t2a = g_t2 + r0 * NA;
        const float* t2b = g_t2 + r1 * NA;
        float s0 = 0.f, s1 = 0.f;
#pragma unroll
        for (int nt = 0; nt < 8; nt++) {
            int n = wn * 64 + nt * 8 + 2 * tg;
            float v0 = va_s[n], v1 = va_s[n + 1];
            s0 += tanhf(acc[mt][nt][0] + t2a[n]) * v0
                + tanhf(acc[mt][nt][1] + t2a[n + 1]) * v1;
            s1 += tanhf(acc[mt][nt][2] + t2b[n]) * v0
                + tanhf(acc[mt][nt][3] + t2b[n + 1]) * v1;
        }
        if (mt == 0) { rs00 = s0; rs01 = s1; } else { rs10 = s0; rs11 = s1; }
    }
    // reduce across the 4 tg lanes sharing a row
#pragma unroll
    for (int off = 1; off <= 2; off <<= 1) {
        rs00 += __shfl_xor_sync(0xffffffffu, rs00, off);
        rs01 += __shfl_xor_sync(0xffffffffu, rs01, off);
        rs10 += __shfl_xor_sync(0xffffffffu, rs10, off);
        rs11 += __shfl_xor_sync(0xffffffffu, rs11, off);
    }
    if (tg == 0) {
        red[wn][wm * 32 + gp]          = rs00;
        red[wn][wm * 32 + gp + 8]      = rs01;
        red[wn][wm * 32 + 16 + gp]     = rs10;
        red[wn][wm * 32 + 16 + gp + 8] = rs11;
    }
    __syncthreads();
    if (tid < 64) {
        g_scores[m0 + tid] =
            red[0][tid] + red[1][tid] + red[2][tid] + red[3][tid] + va_b[0];
    }
}

// ---------------------------------------------------------------------------
// Kernel C: softmax over p for each b; writes weights[p*64+b] to output.
// ---------------------------------------------------------------------------
__global__ __launch_bounds__(256) void softmax_kernel(float* __restrict__ out_w) {
    const int b = blockIdx.x;
    const int tid = threadIdx.x;
    float loc[16];
    float m = -1e30f;
#pragma unroll
    for (int i = 0; i < 16; i++) {
        loc[i] = g_scores[(size_t)(tid + i * 256) * NB + b];
        m = fmaxf(m, loc[i]);
    }
    __shared__ float sm[32];
    __shared__ float ss[32];
#pragma unroll
    for (int off = 16; off; off >>= 1) m = fmaxf(m, __shfl_xor_sync(0xffffffffu, m, off));
    if ((tid & 31) == 0) sm[tid >> 5] = m;
    __syncthreads();
    if (tid < 32) {
        float v = (tid < 8) ? sm[tid] : -1e30f;
#pragma unroll
        for (int off = 4; off; off >>= 1) v = fmaxf(v, __shfl_xor_sync(0xffffffffu, v, off));
        sm[tid] = v;
    }
    __syncthreads();
    m = sm[0];
    float sum = 0.f;
#pragma unroll
    for (int i = 0; i < 16; i++) { loc[i] = __expf(loc[i] - m); sum += loc[i]; }
#pragma unroll
    for (int off = 16; off; off >>= 1) sum += __shfl_xor_sync(0xffffffffu, sum, off);
    if ((tid & 31) == 0) ss[tid >> 5] = sum;
    __syncthreads();
    if (tid < 32) {
        float v = (tid < 8) ? ss[tid] : 0.f;
#pragma unroll
        for (int off = 4; off; off >>= 1) v += __shfl_xor_sync(0xffffffffu, v, off);
        ss[tid] = v;
    }
    __syncthreads();
    const float inv = 1.f / ss[0];
#pragma unroll
    for (int i = 0; i < 16; i++)
        out_w[(size_t)(tid + i * 256) * NB + b] = loc[i] * inv;
}

// ---------------------------------------------------------------------------
// Kernel D: context partials. grid = NSPLIT*NB CTAs, 128 threads (float4).
// ---------------------------------------------------------------------------
__global__ __launch_bounds__(128) void ctx_partial(
    const float* __restrict__ keys, const float* __restrict__ w) {
    const int b = blockIdx.x & (NB - 1);
    const int sp = blockIdx.x >> 6;
    const int c4 = threadIdx.x * 4;
    const int pc = NP / NSPLIT;  // 256
    const int p0 = sp * pc;
    float4 acc = make_float4(0.f, 0.f, 0.f, 0.f);
    for (int p = p0; p < p0 + pc; p += 2) {
        float w0 = __ldg(&w[(size_t)p * NB + b]);
        float w1 = __ldg(&w[(size_t)(p + 1) * NB + b]);
        float4 k0 = *(const float4*)(keys + ((size_t)p * NB + b) * NC + c4);
        float4 k1 = *(const float4*)(keys + ((size_t)(p + 1) * NB + b) * NC + c4);
        acc.x += w0 * k0.x + w1 * k1.x;
        acc.y += w0 * k0.y + w1 * k1.y;
        acc.z += w0 * k0.z + w1 * k1.z;
        acc.w += w0 * k0.w + w1 * k1.w;
    }
    *(float4*)(g_part + ((size_t)(sp * NB + b)) * NC + c4) = acc;
}

// ---------------------------------------------------------------------------
// Kernel E: combine partials -> context[b][c] in output.
// ---------------------------------------------------------------------------
__global__ __launch_bounds__(512) void ctx_combine(float* __restrict__ ctx) {
    const int b = blockIdx.x, c = threadIdx.x;
    float s = 0.f;
#pragma unroll
    for (int sp = 0; sp < NSPLIT; sp++)
        s += g_part[((size_t)(sp * NB + b)) * NC + c];
    ctx[b * NC + c] = s;
}

extern "C" void kernel_launch(void* const* d_in, const int* in_sizes, int n_in,
                              void* d_out, int out_size) {
    const float* keys    = (const float*)d_in[0];
    const float* queries = (const float*)d_in[1];
    const float* Wa_w    = (const float*)d_in[2];
    const float* Wa_b    = (const float*)d_in[3];
    const float* Ua_w    = (const float*)d_in[4];
    const float* Ua_b    = (const float*)d_in[5];
    const float* va_w    = (const float*)d_in[6];
    const float* va_b    = (const float*)d_in[7];

    float* out = (float*)d_out;
    float* ctx = out;                 // context: [1, B, C] = 32768 floats
    float* wts = out + NB * NC;       // weights: [P, B, 1] = 262144 floats

    attn2_kernel<<<NB, NA>>>(queries, Ua_w, Ua_b, Wa_b);
    score_kernel<<<NP, 256>>>(keys, Wa_w, va_w, va_b);
    softmax_kernel<<<NB, 256>>>(wts);
    ctx_partial<<<NSPLIT * NB, 128>>>(keys, wts);
    ctx_combine<<<NB, 512>>>(ctx);
}

// round 3
// speedup vs baseline: 1.3880x; 1.3880x over previous
#include <cuda_runtime.h>
#include <math.h>
#include <stdint.h>

#define NP 4096
#define NB 64
#define NC 512
#define NA 256
#define NSPLIT 32

// Scratch (no device allocation allowed)
__device__ float g_t2[NB * NA];                 // attn2 + Wa_b + Ua_b folded
__device__ float g_scores[NP * NB];             // pre-softmax scores
__device__ float g_part[NSPLIT * NB * NC];      // context partials

// ---------------------------------------------------------------------------
// SMEM layout for score kernel (dynamic)
//   stage s (s=0,1): A tile 128 rows x 80B, then B tile 256 rows x 80B
//   then t2s [64][257] f32, va [256] f32, red [4][128] f32
// ---------------------------------------------------------------------------
#define ROWB 80                       // bytes per smem row (64B data + 16B pad)
#define STG_A (128 * ROWB)            // 10240
#define STG_B (256 * ROWB)            // 20480
#define STG_SZ (STG_A + STG_B)        // 30720
#define OFF_T2 (2 * STG_SZ)           // 61440
#define OFF_VA (OFF_T2 + 64 * 257 * 4)      // 127232
#define OFF_RED (OFF_VA + 256 * 4)          // 128256
#define SMEM_DYN (OFF_RED + 4 * 128 * 4 + 128)

__device__ __forceinline__ uint32_t pack_bf16x2(float lo, float hi) {
    uint32_t r;
    asm("cvt.rn.bf16x2.f32 %0, %1, %2;" : "=r"(r) : "f"(hi), "f"(lo));
    return r;
}

__device__ __forceinline__ void mma_bf16(float c[4], const uint32_t a[4],
                                         uint32_t b0, uint32_t b1) {
    asm volatile(
        "mma.sync.aligned.m16n8k16.row.col.f32.bf16.bf16.f32 "
        "{%0,%1,%2,%3}, {%4,%5,%6,%7}, {%8,%9}, {%0,%1,%2,%3};\n"
        : "+f"(c[0]), "+f"(c[1]), "+f"(c[2]), "+f"(c[3])
        : "r"(a[0]), "r"(a[1]), "r"(a[2]), "r"(a[3]), "r"(b0), "r"(b1));
}

// ---------------------------------------------------------------------------
// Kernel A: t2[b][a] = Ua_w[a,:] . queries[b,:] + Ua_b[a] + Wa_b[a]
// ---------------------------------------------------------------------------
__global__ __launch_bounds__(NA) void attn2_kernel(
    const float* __restrict__ queries, const float* __restrict__ Ua_w,
    const float* __restrict__ Ua_b, const float* __restrict__ Wa_b) {
    __shared__ float qs[NC];
    const int b = blockIdx.x;
    for (int i = threadIdx.x; i < NC; i += blockDim.x) qs[i] = queries[b * NC + i];
    __syncthreads();
    const int a = threadIdx.x;
    const float* ua = Ua_w + (size_t)a * NC;
    float s = 0.f;
#pragma unroll 8
    for (int h = 0; h < NC; h++) s += ua[h] * qs[h];
    g_t2[b * NA + a] = s + Ua_b[a] + Wa_b[a];
}

// ---------------------------------------------------------------------------
// Kernel B: score GEMM, bf16 mma.sync m16n8k16.
// CTA: M=128 (2 pixels x 64 b), N=256 (full A), K=512 in 16 chunks of 32.
// 8 warps = 2(m) x 4(n); warp tile 64x64. Register-staged double buffering.
// ---------------------------------------------------------------------------
__global__ __launch_bounds__(256, 1) void score_bf16(
    const float* __restrict__ keys, const float* __restrict__ Wa_w,
    const float* __restrict__ va_w, const float* __restrict__ va_b) {
    extern __shared__ char smem[];
    float* t2s = (float*)(smem + OFF_T2);
    float* va_s = (float*)(smem + OFF_VA);
    float* red = (float*)(smem + OFF_RED);

    const int tid = threadIdx.x;
    const int warp = tid >> 5, lane = tid & 31;
    const int wm = warp >> 2, wn = warp & 3;       // wm 0..1, wn 0..3
    const int gp = lane >> 2, tg = lane & 3;
    const int m0 = blockIdx.x * 128;

    // loader mapping: each thread handles one 16-float k-segment per row set
    const int lrow = tid >> 1;                      // 0..127
    const int lseg = (tid & 1) * 16;                // 0 or 16

    // preload t2 + va
#pragma unroll
    for (int i = 0; i < 64; i++) {
        int idx = tid + i * 256;                    // 16384 elems
        t2s[(idx >> 8) * 257 + (idx & 255)] = g_t2[idx];
    }
    va_s[tid] = va_w[tid];

    float acc[4][8][4];
#pragma unroll
    for (int a = 0; a < 4; a++)
#pragma unroll
        for (int b = 0; b < 8; b++)
#pragma unroll
            for (int c = 0; c < 4; c++) acc[a][b][c] = 0.f;

    const float* keyrow = keys + (size_t)(m0 + lrow) * NC + lseg;
    const float* warow0 = Wa_w + (size_t)lrow * NC + lseg;
    const float* warow1 = Wa_w + (size_t)(lrow + 128) * NC + lseg;

    float4 ra[4], rb0[4], rb1[4];

    // prologue: chunk 0 -> stage 0
#pragma unroll
    for (int j = 0; j < 4; j++) {
        ra[j] = *(const float4*)(keyrow + 4 * j);
        rb0[j] = *(const float4*)(warow0 + 4 * j);
        rb1[j] = *(const float4*)(warow1 + 4 * j);
    }
    {
        char* sA = smem + 0 * STG_SZ;
        char* sB = sA + STG_A;
#pragma unroll
        for (int j = 0; j < 4; j++) {
            uint32_t w0 = pack_bf16x2(ra[j].x, ra[j].y);
            uint32_t w1 = pack_bf16x2(ra[j].z, ra[j].w);
            *(uint2*)(sA + lrow * ROWB + 2 * (lseg + 4 * j)) = make_uint2(w0, w1);
            w0 = pack_bf16x2(rb0[j].x, rb0[j].y);
            w1 = pack_bf16x2(rb0[j].z, rb0[j].w);
            *(uint2*)(sB + lrow * ROWB + 2 * (lseg + 4 * j)) = make_uint2(w0, w1);
            w0 = pack_bf16x2(rb1[j].x, rb1[j].y);
            w1 = pack_bf16x2(rb1[j].z, rb1[j].w);
            *(uint2*)(sB + (lrow + 128) * ROWB + 2 * (lseg + 4 * j)) = make_uint2(w0, w1);
        }
    }
    __syncthreads();

    for (int c = 0; c < 16; c++) {
        // issue global loads for next chunk (overlap with MMA below)
        if (c + 1 < 16) {
            const int k0 = (c + 1) * 32;
#pragma unroll
            for (int j = 0; j < 4; j++) {
                ra[j] = *(const float4*)(keyrow + k0 + 4 * j);
                rb0[j] = *(const float4*)(warow0 + k0 + 4 * j);
                rb1[j] = *(const float4*)(warow1 + k0 + 4 * j);
            }
        }

        // MMA on stage c%2
        {
            const char* sA = smem + (c & 1) * STG_SZ;
            const char* sB = sA + STG_A;
#pragma unroll
            for (int ks = 0; ks < 32; ks += 16) {
                uint32_t af[4][4];
#pragma unroll
                for (int mt = 0; mt < 4; mt++) {
                    int r0 = wm * 64 + mt * 16 + gp;
                    const char* pa = sA + 2 * ks + 4 * tg;
                    af[mt][0] = *(const uint32_t*)(pa + r0 * ROWB);
                    af[mt][1] = *(const uint32_t*)(pa + (r0 + 8) * ROWB);
                    af[mt][2] = *(const uint32_t*)(pa + r0 * ROWB + 16);
                    af[mt][3] = *(const uint32_t*)(pa + (r0 + 8) * ROWB + 16);
                }
#pragma unroll
                for (int nt = 0; nt < 8; nt++) {
                    int n0 = wn * 64 + nt * 8 + gp;
                    const char* pb = sB + n0 * ROWB + 2 * ks + 4 * tg;
                    uint32_t b0 = *(const uint32_t*)(pb);
                    uint32_t b1 = *(const uint32_t*)(pb + 16);
#pragma unroll
                    for (int mt = 0; mt < 4; mt++)
                        mma_bf16(acc[mt][nt], af[mt], b0, b1);
                }
            }
        }

        // convert + store next chunk into stage (c+1)%2
        if (c + 1 < 16) {
            char* sA = smem + ((c + 1) & 1) * STG_SZ;
            char* sB = sA + STG_A;
#pragma unroll
            for (int j = 0; j < 4; j++) {
                uint32_t w0 = pack_bf16x2(ra[j].x, ra[j].y);
                uint32_t w1 = pack_bf16x2(ra[j].z, ra[j].w);
                *(uint2*)(sA + lrow * ROWB + 2 * (lseg + 4 * j)) = make_uint2(w0, w1);
                w0 = pack_bf16x2(rb0[j].x, rb0[j].y);
                w1 = pack_bf16x2(rb0[j].z, rb0[j].w);
                *(uint2*)(sB + lrow * ROWB + 2 * (lseg + 4 * j)) = make_uint2(w0, w1);
                w0 = pack_bf16x2(rb1[j].x, rb1[j].y);
                w1 = pack_bf16x2(rb1[j].z, rb1[j].w);
                *(uint2*)(sB + (lrow + 128) * ROWB + 2 * (lseg + 4 * j)) = make_uint2(w0, w1);
            }
        }
        __syncthreads();
    }

    // Epilogue: score row r = m0 + local row; b = row & 63.
    const float vb = va_b[0];
#pragma unroll
    for (int mt = 0; mt < 4; mt++) {
        int r0 = wm * 64 + mt * 16 + gp;
        int r1 = r0 + 8;
        const float* t2a = t2s + (r0 & 63) * 257;
        const float* t2b = t2s + (r1 & 63) * 257;
        float s0 = 0.f, s1 = 0.f;
#pragma unroll
        for (int nt = 0; nt < 8; nt++) {
            int n = wn * 64 + nt * 8 + 2 * tg;
            float v0 = va_s[n], v1 = va_s[n + 1];
            float x0 = acc[mt][nt][0] + t2a[n];
            float x1 = acc[mt][nt][1] + t2a[n + 1];
            float x2 = acc[mt][nt][2] + t2b[n];
            float x3 = acc[mt][nt][3] + t2b[n + 1];
            float h0, h1, h2, h3;
            asm("tanh.approx.f32 %0, %1;" : "=f"(h0) : "f"(x0));
            asm("tanh.approx.f32 %0, %1;" : "=f"(h1) : "f"(x1));
            asm("tanh.approx.f32 %0, %1;" : "=f"(h2) : "f"(x2));
            asm("tanh.approx.f32 %0, %1;" : "=f"(h3) : "f"(x3));
            s0 += h0 * v0 + h1 * v1;
            s1 += h2 * v0 + h3 * v1;
        }
        s0 += __shfl_xor_sync(0xffffffffu, s0, 1);
        s0 += __shfl_xor_sync(0xffffffffu, s0, 2);
        s1 += __shfl_xor_sync(0xffffffffu, s1, 1);
        s1 += __shfl_xor_sync(0xffffffffu, s1, 2);
        if (tg == 0) {
            red[wn * 128 + r0] = s0;
            red[wn * 128 + r1] = s1;
        }
    }
    __syncthreads();
    if (tid < 128) {
        g_scores[m0 + tid] =
            red[tid] + red[128 + tid] + red[256 + tid] + red[384 + tid] + vb;
    }
}

// ---------------------------------------------------------------------------
// Kernel C: softmax over p for each b; writes weights[p*64+b] to output.
// ---------------------------------------------------------------------------
__global__ __launch_bounds__(256) void softmax_kernel(float* __restrict__ out_w) {
    const int b = blockIdx.x;
    const int tid = threadIdx.x;
    float loc[16];
    float m = -1e30f;
#pragma unroll
    for (int i = 0; i < 16; i++) {
        loc[i] = g_scores[(size_t)(tid + i * 256) * NB + b];
        m = fmaxf(m, loc[i]);
    }
    __shared__ float sm[32];
    __shared__ float ss[32];
#pragma unroll
    for (int off = 16; off; off >>= 1) m = fmaxf(m, __shfl_xor_sync(0xffffffffu, m, off));
    if ((tid & 31) == 0) sm[tid >> 5] = m;
    __syncthreads();
    if (tid < 32) {
        float v = (tid < 8) ? sm[tid] : -1e30f;
#pragma unroll
        for (int off = 4; off; off >>= 1) v = fmaxf(v, __shfl_xor_sync(0xffffffffu, v, off));
        sm[tid] = v;
    }
    __syncthreads();
    m = sm[0];
    float sum = 0.f;
#pragma unroll
    for (int i = 0; i < 16; i++) { loc[i] = __expf(loc[i] - m); sum += loc[i]; }
#pragma unroll
    for (int off = 16; off; off >>= 1) sum += __shfl_xor_sync(0xffffffffu, sum, off);
    if ((tid & 31) == 0) ss[tid >> 5] = sum;
    __syncthreads();
    if (tid < 32) {
        float v = (tid < 8) ? ss[tid] : 0.f;
#pragma unroll
        for (int off = 4; off; off >>= 1) v += __shfl_xor_sync(0xffffffffu, v, off);
        ss[tid] = v;
    }
    __syncthreads();
    const float inv = 1.f / ss[0];
#pragma unroll
    for (int i = 0; i < 16; i++)
        out_w[(size_t)(tid + i * 256) * NB + b] = loc[i] * inv;
}

// ---------------------------------------------------------------------------
// Kernel D: context partials. grid = NSPLIT*NB CTAs, 128 threads (float4).
// ---------------------------------------------------------------------------
__global__ __launch_bounds__(128) void ctx_partial(
    const float* __restrict__ keys, const float* __restrict__ w) {
    const int b = blockIdx.x & (NB - 1);
    const int sp = blockIdx.x >> 6;
    const int c4 = threadIdx.x * 4;
    const int pc = NP / NSPLIT;  // 128
    const int p0 = sp * pc;
    float4 acc = make_float4(0.f, 0.f, 0.f, 0.f);
    for (int p = p0; p < p0 + pc; p += 4) {
        float w0 = __ldg(&w[(size_t)p * NB + b]);
        float w1 = __ldg(&w[(size_t)(p + 1) * NB + b]);
        float w2 = __ldg(&w[(size_t)(p + 2) * NB + b]);
        float w3 = __ldg(&w[(size_t)(p + 3) * NB + b]);
        float4 k0 = *(const float4*)(keys + ((size_t)p * NB + b) * NC + c4);
        float4 k1 = *(const float4*)(keys + ((size_t)(p + 1) * NB + b) * NC + c4);
        float4 k2 = *(const float4*)(keys + ((size_t)(p + 2) * NB + b) * NC + c4);
        float4 k3 = *(const float4*)(keys + ((size_t)(p + 3) * NB + b) * NC + c4);
        acc.x += w0 * k0.x + w1 * k1.x + w2 * k2.x + w3 * k3.x;
        acc.y += w0 * k0.y + w1 * k1.y + w2 * k2.y + w3 * k3.y;
        acc.z += w0 * k0.z + w1 * k1.z + w2 * k2.z + w3 * k3.z;
        acc.w += w0 * k0.w + w1 * k1.w + w2 * k2.w + w3 * k3.w;
    }
    *(float4*)(g_part + ((size_t)(sp * NB + b)) * NC + c4) = acc;
}

// ---------------------------------------------------------------------------
// Kernel E: combine partials -> context[b][c] in output.
// ---------------------------------------------------------------------------
__global__ __launch_bounds__(512) void ctx_combine(float* __restrict__ ctx) {
    const int b = blockIdx.x, c = threadIdx.x;
    float s = 0.f;
#pragma unroll
    for (int sp = 0; sp < NSPLIT; sp++)
        s += g_part[((size_t)(sp * NB + b)) * NC + c];
    ctx[b * NC + c] = s;
}

extern "C" void kernel_launch(void* const* d_in, const int* in_sizes, int n_in,
                              void* d_out, int out_size) {
    const float* keys    = (const float*)d_in[0];
    const float* queries = (const float*)d_in[1];
    const float* Wa_w    = (const float*)d_in[2];
    const float* Wa_b    = (const float*)d_in[3];
    const float* Ua_w    = (const float*)d_in[4];
    const float* Ua_b    = (const float*)d_in[5];
    const float* va_w    = (const float*)d_in[6];
    const float* va_b    = (const float*)d_in[7];

    float* out = (float*)d_out;
    float* ctx = out;                 // context: [1, B, C] = 32768 floats
    float* wts = out + NB * NC;       // weights: [P, B, 1] = 262144 floats

    cudaFuncSetAttribute(score_bf16, cudaFuncAttributeMaxDynamicSharedMemorySize,
                         SMEM_DYN);

    attn2_kernel<<<NB, NA>>>(queries, Ua_w, Ua_b, Wa_b);
    score_bf16<<<NP * NB / 128, 256, SMEM_DYN>>>(keys, Wa_w, va_w, va_b);
    softmax_kernel<<<NB, 256>>>(wts);
    ctx_partial<<<NSPLIT * NB, 128>>>(keys, wts);
    ctx_combine<<<NB, 512>>>(ctx);
}

// round 4
// speedup vs baseline: 1.4416x; 1.0386x over previous
#include <cuda_runtime.h>
#include <math.h>
#include <stdint.h>

#define NP 4096
#define NB 64
#define NC 512
#define NA 256
#define NSPLIT 16

// Scratch (no device allocation allowed)
__device__ float g_t2[NB * NA];                 // attn2 + Wa_b + Ua_b folded
__device__ float g_scores[NP * NB];             // pre-softmax scores
__device__ float g_part[NSPLIT * NB * NC];      // context partials

// ---------------------------------------------------------------------------
// SMEM layout for score kernel (dynamic)
// ---------------------------------------------------------------------------
#define ROWB 80                       // bytes per smem row (64B data + 16B pad)
#define STG_A (128 * ROWB)            // 10240
#define STG_B (256 * ROWB)            // 20480
#define STG_SZ (STG_A + STG_B)        // 30720
#define OFF_T2 (2 * STG_SZ)           // 61440
#define OFF_VA (OFF_T2 + 64 * 257 * 4)      // 127232
#define OFF_RED (OFF_VA + 256 * 4)          // 128256
#define SMEM_DYN (OFF_RED + 4 * 128 * 4 + 128)

__device__ __forceinline__ uint32_t pack_bf16x2(float lo, float hi) {
    uint32_t r;
    asm("cvt.rn.bf16x2.f32 %0, %1, %2;" : "=r"(r) : "f"(hi), "f"(lo));
    return r;
}

__device__ __forceinline__ void mma_bf16(float c[4], const uint32_t a[4],
                                         uint32_t b0, uint32_t b1) {
    asm volatile(
        "mma.sync.aligned.m16n8k16.row.col.f32.bf16.bf16.f32 "
        "{%0,%1,%2,%3}, {%4,%5,%6,%7}, {%8,%9}, {%0,%1,%2,%3};\n"
        : "+f"(c[0]), "+f"(c[1]), "+f"(c[2]), "+f"(c[3])
        : "r"(a[0]), "r"(a[1]), "r"(a[2]), "r"(a[3]), "r"(b0), "r"(b1));
}

// ---------------------------------------------------------------------------
// Kernel A: t2[b][a] = Ua_w[a,:] . queries[b,:] + Ua_b[a] + Wa_b[a]
// ---------------------------------------------------------------------------
__global__ __launch_bounds__(NA) void attn2_kernel(
    const float* __restrict__ queries, const float* __restrict__ Ua_w,
    const float* __restrict__ Ua_b, const float* __restrict__ Wa_b) {
    __shared__ float qs[NC];
    const int b = blockIdx.x;
    for (int i = threadIdx.x; i < NC; i += blockDim.x) qs[i] = queries[b * NC + i];
    __syncthreads();
    const int a = threadIdx.x;
    const float* ua = Ua_w + (size_t)a * NC;
    float s = 0.f;
#pragma unroll 8
    for (int h = 0; h < NC; h++) s += ua[h] * qs[h];
    g_t2[b * NA + a] = s + Ua_b[a] + Wa_b[a];
}

// ---------------------------------------------------------------------------
// Kernel B: score GEMM, bf16 mma.sync m16n8k16.
// CTA: M=128, N=256, K=512 in 16 chunks of 32. 512 threads.
// 16 warps = 4(m) x 4(n); warp tile 32x64. Register-staged double buffering.
// ---------------------------------------------------------------------------
__global__ __launch_bounds__(512, 1) void score_bf16(
    const float* __restrict__ keys, const float* __restrict__ Wa_w,
    const float* __restrict__ va_w, const float* __restrict__ va_b) {
    extern __shared__ char smem[];
    float* t2s = (float*)(smem + OFF_T2);
    float* va_s = (float*)(smem + OFF_VA);
    float* red = (float*)(smem + OFF_RED);

    const int tid = threadIdx.x;
    const int warp = tid >> 5, lane = tid & 31;
    const int wm = warp >> 2, wn = warp & 3;       // wm 0..3, wn 0..3
    const int gp = lane >> 2, tg = lane & 3;
    const int m0 = blockIdx.x * 128;

    // loader mapping:
    //  A tile (128 rows x 32 f32): thread t -> row=t>>2, seg=(t&3)*8  (8 floats)
    //  B tile (256 rows x 32 f32): thread t -> row=t>>1, seg=(t&1)*16 (16 floats)
    const int arow = tid >> 2, aseg = (tid & 3) * 8;
    const int brow = tid >> 1, bseg = (tid & 1) * 16;

    // preload t2 + va
#pragma unroll
    for (int i = 0; i < 32; i++) {
        int idx = tid + i * 512;                    // 16384 elems
        t2s[(idx >> 8) * 257 + (idx & 255)] = g_t2[idx];
    }
    if (tid < 256) va_s[tid] = va_w[tid];

    float acc[2][8][4];
#pragma unroll
    for (int a = 0; a < 2; a++)
#pragma unroll
        for (int b = 0; b < 8; b++)
#pragma unroll
            for (int c = 0; c < 4; c++) acc[a][b][c] = 0.f;

    const float* keyrow = keys + (size_t)(m0 + arow) * NC + aseg;
    const float* warow = Wa_w + (size_t)brow * NC + bseg;

    float4 ra[2], rb[4];

    // prologue: chunk 0 -> stage 0
    ra[0] = *(const float4*)(keyrow);
    ra[1] = *(const float4*)(keyrow + 4);
#pragma unroll
    for (int j = 0; j < 4; j++) rb[j] = *(const float4*)(warow + 4 * j);
    {
        char* sA = smem;
        char* sB = sA + STG_A;
        uint4 wa;
        wa.x = pack_bf16x2(ra[0].x, ra[0].y);
        wa.y = pack_bf16x2(ra[0].z, ra[0].w);
        wa.z = pack_bf16x2(ra[1].x, ra[1].y);
        wa.w = pack_bf16x2(ra[1].z, ra[1].w);
        *(uint4*)(sA + arow * ROWB + 2 * aseg) = wa;
#pragma unroll
        for (int h = 0; h < 2; h++) {
            uint4 wb;
            wb.x = pack_bf16x2(rb[2 * h].x, rb[2 * h].y);
            wb.y = pack_bf16x2(rb[2 * h].z, rb[2 * h].w);
            wb.z = pack_bf16x2(rb[2 * h + 1].x, rb[2 * h + 1].y);
            wb.w = pack_bf16x2(rb[2 * h + 1].z, rb[2 * h + 1].w);
            *(uint4*)(sB + brow * ROWB + 2 * bseg + 16 * h) = wb;
        }
    }
    __syncthreads();

    for (int c = 0; c < 16; c++) {
        // issue global loads for next chunk (overlap with MMA below)
        if (c + 1 < 16) {
            const int k0 = (c + 1) * 32;
            ra[0] = *(const float4*)(keyrow + k0);
            ra[1] = *(const float4*)(keyrow + k0 + 4);
#pragma unroll
            for (int j = 0; j < 4; j++) rb[j] = *(const float4*)(warow + k0 + 4 * j);
        }

        // MMA on stage c%2
        {
            const char* sA = smem + (c & 1) * STG_SZ;
            const char* sB = sA + STG_A;
#pragma unroll
            for (int ks = 0; ks < 32; ks += 16) {
                uint32_t af[2][4];
#pragma unroll
                for (int mt = 0; mt < 2; mt++) {
                    int r0 = wm * 32 + mt * 16 + gp;
                    const char* pa = sA + 2 * ks + 4 * tg;
                    af[mt][0] = *(const uint32_t*)(pa + r0 * ROWB);
                    af[mt][1] = *(const uint32_t*)(pa + (r0 + 8) * ROWB);
                    af[mt][2] = *(const uint32_t*)(pa + r0 * ROWB + 16);
                    af[mt][3] = *(const uint32_t*)(pa + (r0 + 8) * ROWB + 16);
                }
#pragma unroll
                for (int nt = 0; nt < 8; nt++) {
                    int n0 = wn * 64 + nt * 8 + gp;
                    const char* pb = sB + n0 * ROWB + 2 * ks + 4 * tg;
                    uint32_t b0 = *(const uint32_t*)(pb);
                    uint32_t b1 = *(const uint32_t*)(pb + 16);
                    mma_bf16(acc[0][nt], af[0], b0, b1);
                    mma_bf16(acc[1][nt], af[1], b0, b1);
                }
            }
        }

        // convert + store next chunk into stage (c+1)%2
        if (c + 1 < 16) {
            char* sA = smem + ((c + 1) & 1) * STG_SZ;
            char* sB = sA + STG_A;
            uint4 wa;
            wa.x = pack_bf16x2(ra[0].x, ra[0].y);
            wa.y = pack_bf16x2(ra[0].z, ra[0].w);
            wa.z = pack_bf16x2(ra[1].x, ra[1].y);
            wa.w = pack_bf16x2(ra[1].z, ra[1].w);
            *(uint4*)(sA + arow * ROWB + 2 * aseg) = wa;
#pragma unroll
            for (int h = 0; h < 2; h++) {
                uint4 wb;
                wb.x = pack_bf16x2(rb[2 * h].x, rb[2 * h].y);
                wb.y = pack_bf16x2(rb[2 * h].z, rb[2 * h].w);
                wb.z = pack_bf16x2(rb[2 * h + 1].x, rb[2 * h + 1].y);
                wb.w = pack_bf16x2(rb[2 * h + 1].z, rb[2 * h + 1].w);
                *(uint4*)(sB + brow * ROWB + 2 * bseg + 16 * h) = wb;
            }
        }
        __syncthreads();
    }

    // Epilogue: score row r = m0 + local row; b = row & 63.
    const float vb = va_b[0];
#pragma unroll
    for (int mt = 0; mt < 2; mt++) {
        int r0 = wm * 32 + mt * 16 + gp;
        int r1 = r0 + 8;
        const float* t2a = t2s + (r0 & 63) * 257;
        const float* t2b = t2s + (r1 & 63) * 257;
        float s0 = 0.f, s1 = 0.f;
#pragma unroll
        for (int nt = 0; nt < 8; nt++) {
            int n = wn * 64 + nt * 8 + 2 * tg;
            float v0 = va_s[n], v1 = va_s[n + 1];
            float x0 = acc[mt][nt][0] + t2a[n];
            float x1 = acc[mt][nt][1] + t2a[n + 1];
            float x2 = acc[mt][nt][2] + t2b[n];
            float x3 = acc[mt][nt][3] + t2b[n + 1];
            float h0, h1, h2, h3;
            asm("tanh.approx.f32 %0, %1;" : "=f"(h0) : "f"(x0));
            asm("tanh.approx.f32 %0, %1;" : "=f"(h1) : "f"(x1));
            asm("tanh.approx.f32 %0, %1;" : "=f"(h2) : "f"(x2));
            asm("tanh.approx.f32 %0, %1;" : "=f"(h3) : "f"(x3));
            s0 += h0 * v0 + h1 * v1;
            s1 += h2 * v0 + h3 * v1;
        }
        s0 += __shfl_xor_sync(0xffffffffu, s0, 1);
        s0 += __shfl_xor_sync(0xffffffffu, s0, 2);
        s1 += __shfl_xor_sync(0xffffffffu, s1, 1);
        s1 += __shfl_xor_sync(0xffffffffu, s1, 2);
        if (tg == 0) {
            red[wn * 128 + r0] = s0;
            red[wn * 128 + r1] = s1;
        }
    }
    __syncthreads();
    if (tid < 128) {
        g_scores[m0 + tid] =
            red[tid] + red[128 + tid] + red[256 + tid] + red[384 + tid] + vb;
    }
}

// ---------------------------------------------------------------------------
// Kernel C: softmax over p for each b; writes weights[p*64+b] to output.
// ---------------------------------------------------------------------------
__global__ __launch_bounds__(256) void softmax_kernel(float* __restrict__ out_w) {
    const int b = blockIdx.x;
    const int tid = threadIdx.x;
    float loc[16];
    float m = -1e30f;
#pragma unroll
    for (int i = 0; i < 16; i++) {
        loc[i] = g_scores[(size_t)(tid + i * 256) * NB + b];
        m = fmaxf(m, loc[i]);
    }
    __shared__ float sm[32];
    __shared__ float ss[32];
#pragma unroll
    for (int off = 16; off; off >>= 1) m = fmaxf(m, __shfl_xor_sync(0xffffffffu, m, off));
    if ((tid & 31) == 0) sm[tid >> 5] = m;
    __syncthreads();
    if (tid < 32) {
        float v = (tid < 8) ? sm[tid] : -1e30f;
#pragma unroll
        for (int off = 4; off; off >>= 1) v = fmaxf(v, __shfl_xor_sync(0xffffffffu, v, off));
        sm[tid] = v;
    }
    __syncthreads();
    m = sm[0];
    float sum = 0.f;
#pragma unroll
    for (int i = 0; i < 16; i++) { loc[i] = __expf(loc[i] - m); sum += loc[i]; }
#pragma unroll
    for (int off = 16; off; off >>= 1) sum += __shfl_xor_sync(0xffffffffu, sum, off);
    if ((tid & 31) == 0) ss[tid >> 5] = sum;
    __syncthreads();
    if (tid < 32) {
        float v = (tid < 8) ? ss[tid] : 0.f;
#pragma unroll
        for (int off = 4; off; off >>= 1) v += __shfl_xor_sync(0xffffffffu, v, off);
        ss[tid] = v;
    }
    __syncthreads();
    const float inv = 1.f / ss[0];
#pragma unroll
    for (int i = 0; i < 16; i++)
        out_w[(size_t)(tid + i * 256) * NB + b] = loc[i] * inv;
}

// ---------------------------------------------------------------------------
// Kernel D: context partials. grid = NSPLIT*NB CTAs, 128 threads (float4).
// ---------------------------------------------------------------------------
__global__ __launch_bounds__(128) void ctx_partial(
    const float* __restrict__ keys, const float* __restrict__ w) {
    const int b = blockIdx.x & (NB - 1);
    const int sp = blockIdx.x >> 6;
    const int c4 = threadIdx.x * 4;
    const int pc = NP / NSPLIT;  // 256
    const int p0 = sp * pc;
    float4 acc = make_float4(0.f, 0.f, 0.f, 0.f);
    for (int p = p0; p < p0 + pc; p += 4) {
        float w0 = __ldg(&w[(size_t)p * NB + b]);
        float w1 = __ldg(&w[(size_t)(p + 1) * NB + b]);
        float w2 = __ldg(&w[(size_t)(p + 2) * NB + b]);
        float w3 = __ldg(&w[(size_t)(p + 3) * NB + b]);
        float4 k0 = *(const float4*)(keys + ((size_t)p * NB + b) * NC + c4);
        float4 k1 = *(const float4*)(keys + ((size_t)(p + 1) * NB + b) * NC + c4);
        float4 k2 = *(const float4*)(keys + ((size_t)(p + 2) * NB + b) * NC + c4);
        float4 k3 = *(const float4*)(keys + ((size_t)(p + 3) * NB + b) * NC + c4);
        acc.x += w0 * k0.x + w1 * k1.x + w2 * k2.x + w3 * k3.x;
        acc.y += w0 * k0.y + w1 * k1.y + w2 * k2.y + w3 * k3.y;
        acc.z += w0 * k0.z + w1 * k1.z + w2 * k2.z + w3 * k3.z;
        acc.w += w0 * k0.w + w1 * k1.w + w2 * k2.w + w3 * k3.w;
    }
    *(float4*)(g_part + ((size_t)(sp * NB + b)) * NC + c4) = acc;
}

// ---------------------------------------------------------------------------
// Kernel E: combine partials -> context[b][c] in output.
// ---------------------------------------------------------------------------
__global__ __launch_bounds__(512) void ctx_combine(float* __restrict__ ctx) {
    const int b = blockIdx.x, c = threadIdx.x;
    float s = 0.f;
#pragma unroll
    for (int sp = 0; sp < NSPLIT; sp++)
        s += g_part[((size_t)(sp * NB + b)) * NC + c];
    ctx[b * NC + c] = s;
}

extern "C" void kernel_launch(void* const* d_in, const int* in_sizes, int n_in,
                              void* d_out, int out_size) {
    const float* keys    = (const float*)d_in[0];
    const float* queries = (const float*)d_in[1];
    const float* Wa_w    = (const float*)d_in[2];
    const float* Wa_b    = (const float*)d_in[3];
    const float* Ua_w    = (const float*)d_in[4];
    const float* Ua_b    = (const float*)d_in[5];
    const float* va_w    = (const float*)d_in[6];
    const float* va_b    = (const float*)d_in[7];

    float* out = (float*)d_out;
    float* ctx = out;                 // context: [1, B, C] = 32768 floats
    float* wts = out + NB * NC;       // weights: [P, B, 1] = 262144 floats

    cudaFuncSetAttribute(score_bf16, cudaFuncAttributeMaxDynamicSharedMemorySize,
                         SMEM_DYN);

    attn2_kernel<<<NB, NA>>>(queries, Ua_w, Ua_b, Wa_b);
    score_bf16<<<NP * NB / 128, 512, SMEM_DYN>>>(keys, Wa_w, va_w, va_b);
    softmax_kernel<<<NB, 256>>>(wts);
    ctx_partial<<<NSPLIT * NB, 128>>>(keys, wts);
    ctx_combine<<<NB, 512>>>(ctx);
}

// round 5
// speedup vs baseline: 1.6492x; 1.1440x over previous
#include <cuda_runtime.h>
#include <math.h>
#include <stdint.h>

#define NP 4096
#define NB 64
#define NC 512
#define NA 256
#define NSPLIT 16

// Scratch (no device allocation allowed)
__device__ float g_t2[NB * NA];                 // attn2 + Wa_b + Ua_b folded
__device__ float g_scores[NP * NB];             // pre-softmax scores
__device__ float g_part[NSPLIT * NB * NC];      // context partials

// ---------------------------------------------------------------------------
// SMEM layout for score kernel (dynamic). fp32 staging, 3 stages.
//   Row stride 160B (40 floats): frag LDS.64 pattern is bank-conflict-free.
// ---------------------------------------------------------------------------
#define FSTR 40                        // floats per smem row (32 data + 8 pad)
#define ROWB (FSTR * 4)                // 160
#define STG_A (128 * ROWB)             // 20480
#define STG_B (256 * ROWB)             // 40960
#define STG_SZ (STG_A + STG_B)         // 61440
#define NSTG 3
#define OFF_VA (NSTG * STG_SZ)         // 184320
#define OFF_RED (OFF_VA + 256 * 4)     // 185344
#define SMEM_DYN (OFF_RED + 4 * 128 * 4 + 256)
// t2s reuses stage region (offset 0) after the main loop: [64][260] floats.
#define T2STR 260

__device__ __forceinline__ uint32_t smem_u32(const void* p) {
    uint32_t a;
    asm("{ .reg .u64 t; cvta.to.shared.u64 t, %1; cvt.u32.u64 %0, t; }" : "=r"(a) : "l"(p));
    return a;
}

__device__ __forceinline__ uint32_t pack_bf16x2(float lo, float hi) {
    uint32_t r;
    asm("cvt.rn.bf16x2.f32 %0, %1, %2;" : "=r"(r) : "f"(hi), "f"(lo));
    return r;
}

__device__ __forceinline__ void mma_bf16(float c[4], const uint32_t a[4],
                                         uint32_t b0, uint32_t b1) {
    asm volatile(
        "mma.sync.aligned.m16n8k16.row.col.f32.bf16.bf16.f32 "
        "{%0,%1,%2,%3}, {%4,%5,%6,%7}, {%8,%9}, {%0,%1,%2,%3};\n"
        : "+f"(c[0]), "+f"(c[1]), "+f"(c[2]), "+f"(c[3])
        : "r"(a[0]), "r"(a[1]), "r"(a[2]), "r"(a[3]), "r"(b0), "r"(b1));
}

__device__ __forceinline__ void cp16(uint32_t dst, const void* src) {
    asm volatile("cp.async.cg.shared.global [%0], [%1], 16;" :: "r"(dst), "l"(src));
}
#define CP_COMMIT() asm volatile("cp.async.commit_group;" ::: "memory")
#define CP_WAIT1()  asm volatile("cp.async.wait_group 1;" ::: "memory")

// ---------------------------------------------------------------------------
// Kernel A: t2[b][a] = Ua_w[a,:] . queries[b,:] + Ua_b[a] + Wa_b[a]
// ---------------------------------------------------------------------------
__global__ __launch_bounds__(NA) void attn2_kernel(
    const float* __restrict__ queries, const float* __restrict__ Ua_w,
    const float* __restrict__ Ua_b, const float* __restrict__ Wa_b) {
    __shared__ float qs[NC];
    const int b = blockIdx.x;
    for (int i = threadIdx.x; i < NC; i += blockDim.x) qs[i] = queries[b * NC + i];
    __syncthreads();
    const int a = threadIdx.x;
    const float* ua = Ua_w + (size_t)a * NC;
    float s = 0.f;
#pragma unroll 8
    for (int h = 0; h < NC; h++) s += ua[h] * qs[h];
    g_t2[b * NA + a] = s + Ua_b[a] + Wa_b[a];
}

// ---------------------------------------------------------------------------
// Kernel B: score GEMM, bf16 mma.sync m16n8k16, cp.async 3-stage pipeline.
// CTA: M=128, N=256, K=512 in 16 chunks of 32. 512 threads.
// 16 warps = 4(m) x 4(n); warp tile 32x64. fp32 staged in smem, pack at frag.
// ---------------------------------------------------------------------------
__device__ __forceinline__ void issue_stage(uint32_t sbase, int s,
                                            const float* __restrict__ keys,
                                            const float* __restrict__ Wa,
                                            int m0, int k0, int tid) {
    uint32_t aB = sbase + s * STG_SZ;
    uint32_t bB = aB + STG_A;
#pragma unroll
    for (int j = 0; j < 2; j++) {
        int idx = tid + j * 512;                 // 1024 cp16 for A
        int row = idx >> 3, seg = idx & 7;
        cp16(aB + row * ROWB + seg * 16, keys + (size_t)(m0 + row) * NC + k0 + seg * 4);
    }
#pragma unroll
    for (int j = 0; j < 4; j++) {
        int idx = tid + j * 512;                 // 2048 cp16 for B
        int row = idx >> 3, seg = idx & 7;
        cp16(bB + row * ROWB + seg * 16, Wa + (size_t)row * NC + k0 + seg * 4);
    }
}

__global__ __launch_bounds__(512, 1) void score_bf16(
    const float* __restrict__ keys, const float* __restrict__ Wa_w,
    const float* __restrict__ va_w, const float* __restrict__ va_b) {
    extern __shared__ char smem[];
    const uint32_t sbase = smem_u32(smem);
    float* t2s = (float*)smem;                   // valid AFTER main loop only
    float* va_s = (float*)(smem + OFF_VA);
    float* red = (float*)(smem + OFF_RED);

    const int tid = threadIdx.x;
    const int warp = tid >> 5, lane = tid & 31;
    const int wm = warp >> 2, wn = warp & 3;     // wm 0..3, wn 0..3
    const int gp = lane >> 2, tg = lane & 3;
    const int m0 = blockIdx.x * 128;

    if (tid < 256) va_s[tid] = va_w[tid];

    float acc[2][8][4];
#pragma unroll
    for (int a = 0; a < 2; a++)
#pragma unroll
        for (int b = 0; b < 8; b++)
#pragma unroll
            for (int c = 0; c < 4; c++) acc[a][b][c] = 0.f;

    // prologue: prefetch chunks 0,1
    issue_stage(sbase, 0, keys, Wa_w, m0, 0, tid);
    CP_COMMIT();
    issue_stage(sbase, 1, keys, Wa_w, m0, 32, tid);
    CP_COMMIT();

    for (int c = 0; c < 16; c++) {
        CP_WAIT1();                    // chunk c's stage is resident
        __syncthreads();               // all warps done reading stage (c+2)%3
        if (c + 2 < 16)
            issue_stage(sbase, (c + 2) % NSTG, keys, Wa_w, m0, (c + 2) * 32, tid);
        CP_COMMIT();

        const char* sA = smem + (c % NSTG) * STG_SZ;
        const char* sB = sA + STG_A;
#pragma unroll
        for (int ks = 0; ks < 32; ks += 16) {
            uint32_t af[2][4];
#pragma unroll
            for (int mt = 0; mt < 2; mt++) {
                int r0 = wm * 32 + mt * 16 + gp;
                const char* pa = sA + (ks + 2 * tg) * 4;
                float2 v0 = *(const float2*)(pa + r0 * ROWB);
                float2 v1 = *(const float2*)(pa + (r0 + 8) * ROWB);
                float2 v2 = *(const float2*)(pa + r0 * ROWB + 32);
                float2 v3 = *(const float2*)(pa + (r0 + 8) * ROWB + 32);
                af[mt][0] = pack_bf16x2(v0.x, v0.y);
                af[mt][1] = pack_bf16x2(v1.x, v1.y);
                af[mt][2] = pack_bf16x2(v2.x, v2.y);
                af[mt][3] = pack_bf16x2(v3.x, v3.y);
            }
#pragma unroll
            for (int nt = 0; nt < 8; nt++) {
                int n0 = wn * 64 + nt * 8 + gp;
                const char* pb = sB + n0 * ROWB + (ks + 2 * tg) * 4;
                float2 u0 = *(const float2*)(pb);
                float2 u1 = *(const float2*)(pb + 32);
                uint32_t b0 = pack_bf16x2(u0.x, u0.y);
                uint32_t b1 = pack_bf16x2(u1.x, u1.y);
                mma_bf16(acc[0][nt], af[0], b0, b1);
                mma_bf16(acc[1][nt], af[1], b0, b1);
            }
        }
    }

    // load t2 into (now free) stage region
    __syncthreads();
#pragma unroll
    for (int i = 0; i < 8; i++) {
        int idx4 = tid + i * 512;                // 4096 float4s
        float4 v = *(const float4*)(g_t2 + idx4 * 4);
        int row = idx4 >> 6, col = (idx4 * 4) & 255;
        *(float4*)(t2s + row * T2STR + col) = v;
    }
    __syncthreads();

    // Epilogue: score row r = m0 + local row; b = row & 63.
    const float vb = va_b[0];
#pragma unroll
    for (int mt = 0; mt < 2; mt++) {
        int r0 = wm * 32 + mt * 16 + gp;
        int r1 = r0 + 8;
        const float* t2a = t2s + (r0 & 63) * T2STR;
        const float* t2b = t2s + (r1 & 63) * T2STR;
        float s0 = 0.f, s1 = 0.f;
#pragma unroll
        for (int nt = 0; nt < 8; nt++) {
            int n = wn * 64 + nt * 8 + 2 * tg;
            float v0 = va_s[n], v1 = va_s[n + 1];
            float x0 = acc[mt][nt][0] + t2a[n];
            float x1 = acc[mt][nt][1] + t2a[n + 1];
            float x2 = acc[mt][nt][2] + t2b[n];
            float x3 = acc[mt][nt][3] + t2b[n + 1];
            float h0, h1, h2, h3;
            asm("tanh.approx.f32 %0, %1;" : "=f"(h0) : "f"(x0));
            asm("tanh.approx.f32 %0, %1;" : "=f"(h1) : "f"(x1));
            asm("tanh.approx.f32 %0, %1;" : "=f"(h2) : "f"(x2));
            asm("tanh.approx.f32 %0, %1;" : "=f"(h3) : "f"(x3));
            s0 += h0 * v0 + h1 * v1;
            s1 += h2 * v0 + h3 * v1;
        }
        s0 += __shfl_xor_sync(0xffffffffu, s0, 1);
        s0 += __shfl_xor_sync(0xffffffffu, s0, 2);
        s1 += __shfl_xor_sync(0xffffffffu, s1, 1);
        s1 += __shfl_xor_sync(0xffffffffu, s1, 2);
        if (tg == 0) {
            red[wn * 128 + r0] = s0;
            red[wn * 128 + r1] = s1;
        }
    }
    __syncthreads();
    if (tid < 128) {
        g_scores[m0 + tid] =
            red[tid] + red[128 + tid] + red[256 + tid] + red[384 + tid] + vb;
    }
}

// ---------------------------------------------------------------------------
// Kernel C: softmax over p for each b; writes weights[p*64+b] to output.
// ---------------------------------------------------------------------------
__global__ __launch_bounds__(256) void softmax_kernel(float* __restrict__ out_w) {
    const int b = blockIdx.x;
    const int tid = threadIdx.x;
    float loc[16];
    float m = -1e30f;
#pragma unroll
    for (int i = 0; i < 16; i++) {
        loc[i] = g_scores[(size_t)(tid + i * 256) * NB + b];
        m = fmaxf(m, loc[i]);
    }
    __shared__ float sm[32];
    __shared__ float ss[32];
#pragma unroll
    for (int off = 16; off; off >>= 1) m = fmaxf(m, __shfl_xor_sync(0xffffffffu, m, off));
    if ((tid & 31) == 0) sm[tid >> 5] = m;
    __syncthreads();
    if (tid < 32) {
        float v = (tid < 8) ? sm[tid] : -1e30f;
#pragma unroll
        for (int off = 4; off; off >>= 1) v = fmaxf(v, __shfl_xor_sync(0xffffffffu, v, off));
        sm[tid] = v;
    }
    __syncthreads();
    m = sm[0];
    float sum = 0.f;
#pragma unroll
    for (int i = 0; i < 16; i++) { loc[i] = __expf(loc[i] - m); sum += loc[i]; }
#pragma unroll
    for (int off = 16; off; off >>= 1) sum += __shfl_xor_sync(0xffffffffu, sum, off);
    if ((tid & 31) == 0) ss[tid >> 5] = sum;
    __syncthreads();
    if (tid < 32) {
        float v = (tid < 8) ? ss[tid] : 0.f;
#pragma unroll
        for (int off = 4; off; off >>= 1) v += __shfl_xor_sync(0xffffffffu, v, off);
        ss[tid] = v;
    }
    __syncthreads();
    const float inv = 1.f / ss[0];
#pragma unroll
    for (int i = 0; i < 16; i++)
        out_w[(size_t)(tid + i * 256) * NB + b] = loc[i] * inv;
}

// ---------------------------------------------------------------------------
// Kernel D: context partials. grid = NSPLIT*NB CTAs, 128 threads (float4).
// ---------------------------------------------------------------------------
__global__ __launch_bounds__(128) void ctx_partial(
    const float* __restrict__ keys, const float* __restrict__ w) {
    const int b = blockIdx.x & (NB - 1);
    const int sp = blockIdx.x >> 6;
    const int c4 = threadIdx.x * 4;
    const int pc = NP / NSPLIT;  // 256
    const int p0 = sp * pc;
    float4 acc = make_float4(0.f, 0.f, 0.f, 0.f);
    for (int p = p0; p < p0 + pc; p += 4) {
        float w0 = __ldg(&w[(size_t)p * NB + b]);
        float w1 = __ldg(&w[(size_t)(p + 1) * NB + b]);
        float w2 = __ldg(&w[(size_t)(p + 2) * NB + b]);
        float w3 = __ldg(&w[(size_t)(p + 3) * NB + b]);
        float4 k0 = *(const float4*)(keys + ((size_t)p * NB + b) * NC + c4);
        float4 k1 = *(const float4*)(keys + ((size_t)(p + 1) * NB + b) * NC + c4);
        float4 k2 = *(const float4*)(keys + ((size_t)(p + 2) * NB + b) * NC + c4);
        float4 k3 = *(const float4*)(keys + ((size_t)(p + 3) * NB + b) * NC + c4);
        acc.x += w0 * k0.x + w1 * k1.x + w2 * k2.x + w3 * k3.x;
        acc.y += w0 * k0.y + w1 * k1.y + w2 * k2.y + w3 * k3.y;
        acc.z += w0 * k0.z + w1 * k1.z + w2 * k2.z + w3 * k3.z;
        acc.w += w0 * k0.w + w1 * k1.w + w2 * k2.w + w3 * k3.w;
    }
    *(float4*)(g_part + ((size_t)(sp * NB + b)) * NC + c4) = acc;
}

// ---------------------------------------------------------------------------
// Kernel E: combine partials -> context[b][c] in output.
// ---------------------------------------------------------------------------
__global__ __launch_bounds__(512) void ctx_combine(float* __restrict__ ctx) {
    const int b = blockIdx.x, c = threadIdx.x;
    float s = 0.f;
#pragma unroll
    for (int sp = 0; sp < NSPLIT; sp++)
        s += g_part[((size_t)(sp * NB + b)) * NC + c];
    ctx[b * NC + c] = s;
}

extern "C" void kernel_launch(void* const* d_in, const int* in_sizes, int n_in,
                              void* d_out, int out_size) {
    const float* keys    = (const float*)d_in[0];
    const float* queries = (const float*)d_in[1];
    const float* Wa_w    = (const float*)d_in[2];
    const float* Wa_b    = (const float*)d_in[3];
    const float* Ua_w    = (const float*)d_in[4];
    const float* Ua_b    = (const float*)d_in[5];
    const float* va_w    = (const float*)d_in[6];
    const float* va_b    = (const float*)d_in[7];

    float* out = (float*)d_out;
    float* ctx = out;                 // context: [1, B, C] = 32768 floats
    float* wts = out + NB * NC;       // weights: [P, B, 1] = 262144 floats

    cudaFuncSetAttribute(score_bf16, cudaFuncAttributeMaxDynamicSharedMemorySize,
                         SMEM_DYN);

    attn2_kernel<<<NB, NA>>>(queries, Ua_w, Ua_b, Wa_b);
    score_bf16<<<NP * NB / 128, 512, SMEM_DYN>>>(keys, Wa_w, va_w, va_b);
    softmax_kernel<<<NB, 256>>>(wts);
    ctx_partial<<<NSPLIT * NB, 128>>>(keys, wts);
    ctx_combine<<<NB, 512>>>(ctx);
}

// round 6
// speedup vs baseline: 1.7811x; 1.0800x over previous
#include <cuda_runtime.h>
#include <math.h>
#include <stdint.h>

#define NP 4096
#define NB 64
#define NC 512
#define NA 256
#define NSPLIT 16

// Scratch (no device allocation allowed)
__device__ float g_t2[NB * NA];                 // attn2 + Wa_b + Ua_b folded
__device__ float g_scores[NP * NB];             // pre-softmax scores
__device__ float g_part[NSPLIT * NB * NC];      // context partials
__device__ uint32_t g_wab[NA * NC / 2];         // Wa_w as bf16x2 (256 KB)

// ---------------------------------------------------------------------------
// SMEM layout for score kernel (dynamic). A fp32 (160B rows), B bf16 (80B rows).
// ---------------------------------------------------------------------------
#define ROWB_A 160                     // A row stride bytes (32 f32 + pad)
#define ROWB_B 80                      // B row stride bytes (32 bf16 + pad)
#define STG_A (128 * ROWB_A)           // 20480
#define STG_B (256 * ROWB_B)           // 20480
#define STG_SZ (STG_A + STG_B)         // 40960
#define NSTG 3
#define OFF_VA (NSTG * STG_SZ)         // 122880
#define OFF_RED (OFF_VA + 256 * 4)     // 123904
#define SMEM_DYN (OFF_RED + 4 * 128 * 4 + 256)
// t2s reuses stage region (offset 0) after the main loop: [64][260] floats.
#define T2STR 260

__device__ __forceinline__ uint32_t smem_u32(const void* p) {
    uint32_t a;
    asm("{ .reg .u64 t; cvta.to.shared.u64 t, %1; cvt.u32.u64 %0, t; }" : "=r"(a) : "l"(p));
    return a;
}

__device__ __forceinline__ uint32_t pack_bf16x2(float lo, float hi) {
    uint32_t r;
    asm("cvt.rn.bf16x2.f32 %0, %1, %2;" : "=r"(r) : "f"(hi), "f"(lo));
    return r;
}

__device__ __forceinline__ void mma_bf16(float c[4], const uint32_t a[4],
                                         uint32_t b0, uint32_t b1) {
    asm volatile(
        "mma.sync.aligned.m16n8k16.row.col.f32.bf16.bf16.f32 "
        "{%0,%1,%2,%3}, {%4,%5,%6,%7}, {%8,%9}, {%0,%1,%2,%3};\n"
        : "+f"(c[0]), "+f"(c[1]), "+f"(c[2]), "+f"(c[3])
        : "r"(a[0]), "r"(a[1]), "r"(a[2]), "r"(a[3]), "r"(b0), "r"(b1));
}

__device__ __forceinline__ void ldm_x4(uint32_t& r0, uint32_t& r1,
                                       uint32_t& r2, uint32_t& r3, uint32_t addr) {
    asm volatile("ldmatrix.sync.aligned.m8n8.x4.shared.b16 {%0,%1,%2,%3}, [%4];"
                 : "=r"(r0), "=r"(r1), "=r"(r2), "=r"(r3) : "r"(addr));
}

__device__ __forceinline__ void cp16(uint32_t dst, const void* src) {
    asm volatile("cp.async.cg.shared.global [%0], [%1], 16;" :: "r"(dst), "l"(src));
}
#define CP_COMMIT() asm volatile("cp.async.commit_group;" ::: "memory")
#define CP_WAIT1()  asm volatile("cp.async.wait_group 1;" ::: "memory")

// ---------------------------------------------------------------------------
// Kernel P: Wa_w fp32 -> bf16x2 (same cvt.rn rounding as before)
// ---------------------------------------------------------------------------
__global__ __launch_bounds__(256) void wa_cvt(const float* __restrict__ Wa_w) {
    int idx = blockIdx.x * 256 + threadIdx.x;   // 0..65535
    float2 v = *(const float2*)(Wa_w + idx * 2);
    g_wab[idx] = pack_bf16x2(v.x, v.y);
}

// ---------------------------------------------------------------------------
// Kernel A: t2[b][a] = Ua_w[a,:] . queries[b,:] + Ua_b[a] + Wa_b[a]
// ---------------------------------------------------------------------------
__global__ __launch_bounds__(NA) void attn2_kernel(
    const float* __restrict__ queries, const float* __restrict__ Ua_w,
    const float* __restrict__ Ua_b, const float* __restrict__ Wa_b) {
    __shared__ float qs[NC];
    const int b = blockIdx.x;
    for (int i = threadIdx.x; i < NC; i += blockDim.x) qs[i] = queries[b * NC + i];
    __syncthreads();
    const int a = threadIdx.x;
    const float* ua = Ua_w + (size_t)a * NC;
    float s = 0.f;
#pragma unroll 8
    for (int h = 0; h < NC; h++) s += ua[h] * qs[h];
    g_t2[b * NA + a] = s + Ua_b[a] + Wa_b[a];
}

// ---------------------------------------------------------------------------
// Kernel B: score GEMM. A fp32->pack at frag; B bf16 via ldmatrix.
// CTA: M=128, N=256, K=512 in 16 chunks of 32. 512 threads, 16 warps 4x4,
// warp tile 32x64. cp.async 3-stage pipeline.
// ---------------------------------------------------------------------------
__device__ __forceinline__ void issue_stage(uint32_t sbase, int s,
                                            const float* __restrict__ keys,
                                            int m0, int k0, int tid) {
    uint32_t aB = sbase + s * STG_SZ;
    uint32_t bB = aB + STG_A;
#pragma unroll
    for (int j = 0; j < 2; j++) {
        int idx = tid + j * 512;                 // 1024 cp16 for A (fp32)
        int row = idx >> 3, seg = idx & 7;
        cp16(aB + row * ROWB_A + seg * 16,
             keys + (size_t)(m0 + row) * NC + k0 + seg * 4);
    }
    const char* wab = (const char*)g_wab;
#pragma unroll
    for (int j = 0; j < 2; j++) {
        int idx = tid + j * 512;                 // 1024 cp16 for B (bf16)
        int row = idx >> 2, seg = idx & 3;       // 256 rows x 4 segs of 16B
        cp16(bB + row * ROWB_B + seg * 16,
             wab + (size_t)row * (NC * 2) + k0 * 2 + seg * 16);
    }
}

__global__ __launch_bounds__(512, 1) void score_bf16(
    const float* __restrict__ keys,
    const float* __restrict__ va_w, const float* __restrict__ va_b) {
    extern __shared__ char smem[];
    const uint32_t sbase = smem_u32(smem);
    float* t2s = (float*)smem;                   // valid AFTER main loop only
    float* va_s = (float*)(smem + OFF_VA);
    float* red = (float*)(smem + OFF_RED);

    const int tid = threadIdx.x;
    const int warp = tid >> 5, lane = tid & 31;
    const int wm = warp >> 2, wn = warp & 3;     // wm 0..3, wn 0..3
    const int gp = lane >> 2, tg = lane & 3;
    const int m0 = blockIdx.x * 128;

    // per-lane ldmatrix row address component:
    //   matrix m = lane/8 -> (nt_sub = m>>1 adds 8 rows, kh = m&1 adds 16B)
    const int lm = lane >> 3, lr = lane & 7;
    const uint32_t b_lane_off =
        (uint32_t)((wn * 64 + (lm >> 1) * 8 + lr) * ROWB_B + (lm & 1) * 16);

    if (tid < 256) va_s[tid] = va_w[tid];

    float acc[2][8][4];
#pragma unroll
    for (int a = 0; a < 2; a++)
#pragma unroll
        for (int b = 0; b < 8; b++)
#pragma unroll
            for (int c = 0; c < 4; c++) acc[a][b][c] = 0.f;

    // prologue: prefetch chunks 0,1
    issue_stage(sbase, 0, keys, m0, 0, tid);
    CP_COMMIT();
    issue_stage(sbase, 1, keys, m0, 32, tid);
    CP_COMMIT();

    for (int c = 0; c < 16; c++) {
        CP_WAIT1();                    // chunk c's stage is resident
        __syncthreads();               // all warps done reading stage (c+2)%3
        if (c + 2 < 16)
            issue_stage(sbase, (c + 2) % NSTG, keys, m0, (c + 2) * 32, tid);
        CP_COMMIT();

        const char* sA = smem + (c % NSTG) * STG_SZ;
        const uint32_t bbase = sbase + (c % NSTG) * STG_SZ + STG_A + b_lane_off;
#pragma unroll
        for (int ks = 0; ks < 32; ks += 16) {
            uint32_t af[2][4];
#pragma unroll
            for (int mt = 0; mt < 2; mt++) {
                int r0 = wm * 32 + mt * 16 + gp;
                const char* pa = sA + (ks + 2 * tg) * 4;
                float2 v0 = *(const float2*)(pa + r0 * ROWB_A);
                float2 v1 = *(const float2*)(pa + (r0 + 8) * ROWB_A);
                float2 v2 = *(const float2*)(pa + r0 * ROWB_A + 32);
                float2 v3 = *(const float2*)(pa + (r0 + 8) * ROWB_A + 32);
                af[mt][0] = pack_bf16x2(v0.x, v0.y);
                af[mt][1] = pack_bf16x2(v1.x, v1.y);
                af[mt][2] = pack_bf16x2(v2.x, v2.y);
                af[mt][3] = pack_bf16x2(v3.x, v3.y);
            }
            uint32_t bfr[8][2];
#pragma unroll
            for (int g = 0; g < 4; g++) {
                ldm_x4(bfr[2 * g][0], bfr[2 * g][1],
                       bfr[2 * g + 1][0], bfr[2 * g + 1][1],
                       bbase + (uint32_t)(g * 16 * ROWB_B + ks * 2));
            }
#pragma unroll
            for (int nt = 0; nt < 8; nt++) {
                mma_bf16(acc[0][nt], af[0], bfr[nt][0], bfr[nt][1]);
                mma_bf16(acc[1][nt], af[1], bfr[nt][0], bfr[nt][1]);
            }
        }
    }

    // load t2 into (now free) stage region
    __syncthreads();
#pragma unroll
    for (int i = 0; i < 8; i++) {
        int idx4 = tid + i * 512;                // 4096 float4s
        float4 v = *(const float4*)(g_t2 + idx4 * 4);
        int row = idx4 >> 6, col = (idx4 * 4) & 255;
        *(float4*)(t2s + row * T2STR + col) = v;
    }
    __syncthreads();

    // Epilogue: score row r = m0 + local row; b = row & 63.
    const float vb = va_b[0];
#pragma unroll
    for (int mt = 0; mt < 2; mt++) {
        int r0 = wm * 32 + mt * 16 + gp;
        int r1 = r0 + 8;
        const float* t2a = t2s + (r0 & 63) * T2STR;
        const float* t2b = t2s + (r1 & 63) * T2STR;
        float s0 = 0.f, s1 = 0.f;
#pragma unroll
        for (int nt = 0; nt < 8; nt++) {
            int n = wn * 64 + nt * 8 + 2 * tg;
            float v0 = va_s[n], v1 = va_s[n + 1];
            float x0 = acc[mt][nt][0] + t2a[n];
            float x1 = acc[mt][nt][1] + t2a[n + 1];
            float x2 = acc[mt][nt][2] + t2b[n];
            float x3 = acc[mt][nt][3] + t2b[n + 1];
            float h0, h1, h2, h3;
            asm("tanh.approx.f32 %0, %1;" : "=f"(h0) : "f"(x0));
            asm("tanh.approx.f32 %0, %1;" : "=f"(h1) : "f"(x1));
            asm("tanh.approx.f32 %0, %1;" : "=f"(h2) : "f"(x2));
            asm("tanh.approx.f32 %0, %1;" : "=f"(h3) : "f"(x3));
            s0 += h0 * v0 + h1 * v1;
            s1 += h2 * v0 + h3 * v1;
        }
        s0 += __shfl_xor_sync(0xffffffffu, s0, 1);
        s0 += __shfl_xor_sync(0xffffffffu, s0, 2);
        s1 += __shfl_xor_sync(0xffffffffu, s1, 1);
        s1 += __shfl_xor_sync(0xffffffffu, s1, 2);
        if (tg == 0) {
            red[wn * 128 + r0] = s0;
            red[wn * 128 + r1] = s1;
        }
    }
    __syncthreads();
    if (tid < 128) {
        g_scores[m0 + tid] =
            red[tid] + red[128 + tid] + red[256 + tid] + red[384 + tid] + vb;
    }
}

// ---------------------------------------------------------------------------
// Kernel C: softmax over p for each b; writes weights[p*64+b] to output.
// ---------------------------------------------------------------------------
__global__ __launch_bounds__(256) void softmax_kernel(float* __restrict__ out_w) {
    const int b = blockIdx.x;
    const int tid = threadIdx.x;
    float loc[16];
    float m = -1e30f;
#pragma unroll
    for (int i = 0; i < 16; i++) {
        loc[i] = g_scores[(size_t)(tid + i * 256) * NB + b];
        m = fmaxf(m, loc[i]);
    }
    __shared__ float sm[32];
    __shared__ float ss[32];
#pragma unroll
    for (int off = 16; off; off >>= 1) m = fmaxf(m, __shfl_xor_sync(0xffffffffu, m, off));
    if ((tid & 31) == 0) sm[tid >> 5] = m;
    __syncthreads();
    if (tid < 32) {
        float v = (tid < 8) ? sm[tid] : -1e30f;
#pragma unroll
        for (int off = 4; off; off >>= 1) v = fmaxf(v, __shfl_xor_sync(0xffffffffu, v, off));
        sm[tid] = v;
    }
    __syncthreads();
    m = sm[0];
    float sum = 0.f;
#pragma unroll
    for (int i = 0; i < 16; i++) { loc[i] = __expf(loc[i] - m); sum += loc[i]; }
#pragma unroll
    for (int off = 16; off; off >>= 1) sum += __shfl_xor_sync(0xffffffffu, sum, off);
    if ((tid & 31) == 0) ss[tid >> 5] = sum;
    __syncthreads();
    if (tid < 32) {
        float v = (tid < 8) ? ss[tid] : 0.f;
#pragma unroll
        for (int off = 4; off; off >>= 1) v += __shfl_xor_sync(0xffffffffu, v, off);
        ss[tid] = v;
    }
    __syncthreads();
    const float inv = 1.f / ss[0];
#pragma unroll
    for (int i = 0; i < 16; i++)
        out_w[(size_t)(tid + i * 256) * NB + b] = loc[i] * inv;
}

// ---------------------------------------------------------------------------
// Kernel D: context partials. grid = NSPLIT*NB CTAs, 128 threads (float4).
// ---------------------------------------------------------------------------
__global__ __launch_bounds__(128) void ctx_partial(
    const float* __restrict__ keys, const float* __restrict__ w) {
    const int b = blockIdx.x & (NB - 1);
    const int sp = blockIdx.x >> 6;
    const int c4 = threadIdx.x * 4;
    const int pc = NP / NSPLIT;  // 256
    const int p0 = sp * pc;
    float4 acc = make_float4(0.f, 0.f, 0.f, 0.f);
    for (int p = p0; p < p0 + pc; p += 4) {
        float w0 = __ldg(&w[(size_t)p * NB + b]);
        float w1 = __ldg(&w[(size_t)(p + 1) * NB + b]);
        float w2 = __ldg(&w[(size_t)(p + 2) * NB + b]);
        float w3 = __ldg(&w[(size_t)(p + 3) * NB + b]);
        float4 k0 = *(const float4*)(keys + ((size_t)p * NB + b) * NC + c4);
        float4 k1 = *(const float4*)(keys + ((size_t)(p + 1) * NB + b) * NC + c4);
        float4 k2 = *(const float4*)(keys + ((size_t)(p + 2) * NB + b) * NC + c4);
        float4 k3 = *(const float4*)(keys + ((size_t)(p + 3) * NB + b) * NC + c4);
        acc.x += w0 * k0.x + w1 * k1.x + w2 * k2.x + w3 * k3.x;
        acc.y += w0 * k0.y + w1 * k1.y + w2 * k2.y + w3 * k3.y;
        acc.z += w0 * k0.z + w1 * k1.z + w2 * k2.z + w3 * k3.z;
        acc.w += w0 * k0.w + w1 * k1.w + w2 * k2.w + w3 * k3.w;
    }
    *(float4*)(g_part + ((size_t)(sp * NB + b)) * NC + c4) = acc;
}

// ---------------------------------------------------------------------------
// Kernel E: combine partials -> context[b][c] in output.
// ---------------------------------------------------------------------------
__global__ __launch_bounds__(512) void ctx_combine(float* __restrict__ ctx) {
    const int b = blockIdx.x, c = threadIdx.x;
    float s = 0.f;
#pragma unroll
    for (int sp = 0; sp < NSPLIT; sp++)
        s += g_part[((size_t)(sp * NB + b)) * NC + c];
    ctx[b * NC + c] = s;
}

extern "C" void kernel_launch(void* const* d_in, const int* in_sizes, int n_in,
                              void* d_out, int out_size) {
    const float* keys    = (const float*)d_in[0];
    const float* queries = (const float*)d_in[1];
    const float* Wa_w    = (const float*)d_in[2];
    const float* Wa_b    = (const float*)d_in[3];
    const float* Ua_w    = (const float*)d_in[4];
    const float* Ua_b    = (const float*)d_in[5];
    const float* va_w    = (const float*)d_in[6];
    const float* va_b    = (const float*)d_in[7];

    float* out = (float*)d_out;
    float* ctx = out;                 // context: [1, B, C] = 32768 floats
    float* wts = out + NB * NC;       // weights: [P, B, 1] = 262144 floats

    cudaFuncSetAttribute(score_bf16, cudaFuncAttributeMaxDynamicSharedMemorySize,
                         SMEM_DYN);

    wa_cvt<<<NA * NC / 2 / 256, 256>>>(Wa_w);
    attn2_kernel<<<NB, NA>>>(queries, Ua_w, Ua_b, Wa_b);
    score_bf16<<<NP * NB / 128, 512, SMEM_DYN>>>(keys, va_w, va_b);
    softmax_kernel<<<NB, 256>>>(wts);
    ctx_partial<<<NSPLIT * NB, 128>>>(keys, wts);
    ctx_combine<<<NB, 512>>>(ctx);
}

// round 7
// speedup vs baseline: 1.8910x; 1.0617x over previous
#include <cuda_runtime.h>
#include <math.h>
#include <stdint.h>

#define NP 4096
#define NB 64
#define NC 512
#define NA 256
#define NSPLIT 16

// Scratch (no device allocation allowed)
__device__ float g_t2[NB * NA];                 // attn2 + Wa_b + Ua_b folded
__device__ float g_scores[NP * NB];             // pre-softmax scores
__device__ float g_part[NSPLIT * NB * NC];      // context partials
__device__ uint32_t g_wab[NA * NC / 2];         // Wa_w as bf16x2 (256 KB)

// ---------------------------------------------------------------------------
// SMEM layout for score kernel (dynamic). A fp32 (160B rows), B bf16 (80B rows).
// M-tile = 64 rows -> 2 CTAs/SM.
// ---------------------------------------------------------------------------
#define ROWB_A 160                     // A row stride bytes (32 f32 + pad)
#define ROWB_B 80                      // B row stride bytes (32 bf16 + pad)
#define STG_A (64 * ROWB_A)            // 10240
#define STG_B (256 * ROWB_B)           // 20480
#define STG_SZ (STG_A + STG_B)         // 30720
#define NSTG 3
#define OFF_VA (NSTG * STG_SZ)         // 92160
#define OFF_RED (OFF_VA + 256 * 4)     // 93184
#define SMEM_DYN (OFF_RED + 4 * 64 * 4 + 256)   // 94464
// t2s reuses stage region (offset 0) after the main loop: [64][260] floats.
#define T2STR 260

__device__ __forceinline__ uint32_t smem_u32(const void* p) {
    uint32_t a;
    asm("{ .reg .u64 t; cvta.to.shared.u64 t, %1; cvt.u32.u64 %0, t; }" : "=r"(a) : "l"(p));
    return a;
}

__device__ __forceinline__ uint32_t pack_bf16x2(float lo, float hi) {
    uint32_t r;
    asm("cvt.rn.bf16x2.f32 %0, %1, %2;" : "=r"(r) : "f"(hi), "f"(lo));
    return r;
}

__device__ __forceinline__ void mma_bf16(float c[4], const uint32_t a[4],
                                         uint32_t b0, uint32_t b1) {
    asm volatile(
        "mma.sync.aligned.m16n8k16.row.col.f32.bf16.bf16.f32 "
        "{%0,%1,%2,%3}, {%4,%5,%6,%7}, {%8,%9}, {%0,%1,%2,%3};\n"
        : "+f"(c[0]), "+f"(c[1]), "+f"(c[2]), "+f"(c[3])
        : "r"(a[0]), "r"(a[1]), "r"(a[2]), "r"(a[3]), "r"(b0), "r"(b1));
}

__device__ __forceinline__ void ldm_x4(uint32_t& r0, uint32_t& r1,
                                       uint32_t& r2, uint32_t& r3, uint32_t addr) {
    asm volatile("ldmatrix.sync.aligned.m8n8.x4.shared.b16 {%0,%1,%2,%3}, [%4];"
                 : "=r"(r0), "=r"(r1), "=r"(r2), "=r"(r3) : "r"(addr));
}

__device__ __forceinline__ void cp16(uint32_t dst, const void* src) {
    asm volatile("cp.async.cg.shared.global [%0], [%1], 16;" :: "r"(dst), "l"(src));
}
#define CP_COMMIT() asm volatile("cp.async.commit_group;" ::: "memory")
#define CP_WAIT1()  asm volatile("cp.async.wait_group 1;" ::: "memory")

// ---------------------------------------------------------------------------
// Kernel P: Wa_w fp32 -> bf16x2 (same cvt.rn rounding as before)
// ---------------------------------------------------------------------------
__global__ __launch_bounds__(256) void wa_cvt(const float* __restrict__ Wa_w) {
    int idx = blockIdx.x * 256 + threadIdx.x;   // 0..65535
    float2 v = *(const float2*)(Wa_w + idx * 2);
    g_wab[idx] = pack_bf16x2(v.x, v.y);
}

// ---------------------------------------------------------------------------
// Kernel A: t2[b][a] = Ua_w[a,:] . queries[b,:] + Ua_b[a] + Wa_b[a]
// ---------------------------------------------------------------------------
__global__ __launch_bounds__(NA) void attn2_kernel(
    const float* __restrict__ queries, const float* __restrict__ Ua_w,
    const float* __restrict__ Ua_b, const float* __restrict__ Wa_b) {
    __shared__ float qs[NC];
    const int b = blockIdx.x;
    for (int i = threadIdx.x; i < NC; i += blockDim.x) qs[i] = queries[b * NC + i];
    __syncthreads();
    const int a = threadIdx.x;
    const float* ua = Ua_w + (size_t)a * NC;
    float s = 0.f;
#pragma unroll 8
    for (int h = 0; h < NC; h++) s += ua[h] * qs[h];
    g_t2[b * NA + a] = s + Ua_b[a] + Wa_b[a];
}

// ---------------------------------------------------------------------------
// Kernel B: score GEMM. A fp32->pack at frag; B bf16 via ldmatrix.
// CTA: M=64 (one pixel, all b), N=256, K=512 in 16 chunks of 32. 256 threads,
// 8 warps = 2(m) x 4(n), warp tile 32x64. cp.async 3-stage pipeline, 2 CTAs/SM.
// ---------------------------------------------------------------------------
__device__ __forceinline__ void issue_stage(uint32_t sbase, int s,
                                            const float* __restrict__ keys,
                                            int m0, int k0, int tid) {
    uint32_t aB = sbase + s * STG_SZ;
    uint32_t bB = aB + STG_A;
#pragma unroll
    for (int j = 0; j < 2; j++) {
        int idx = tid + j * 256;                 // 512 cp16 for A (fp32, 64 rows)
        int row = idx >> 3, seg = idx & 7;
        cp16(aB + row * ROWB_A + seg * 16,
             keys + (size_t)(m0 + row) * NC + k0 + seg * 4);
    }
    const char* wab = (const char*)g_wab;
#pragma unroll
    for (int j = 0; j < 4; j++) {
        int idx = tid + j * 256;                 // 1024 cp16 for B (bf16, 256 rows)
        int row = idx >> 2, seg = idx & 3;
        cp16(bB + row * ROWB_B + seg * 16,
             wab + (size_t)row * (NC * 2) + k0 * 2 + seg * 16);
    }
}

__global__ __launch_bounds__(256, 2) void score_bf16(
    const float* __restrict__ keys,
    const float* __restrict__ va_w, const float* __restrict__ va_b) {
    extern __shared__ char smem[];
    const uint32_t sbase = smem_u32(smem);
    float* t2s = (float*)smem;                   // valid AFTER main loop only
    float* va_s = (float*)(smem + OFF_VA);
    float* red = (float*)(smem + OFF_RED);

    const int tid = threadIdx.x;
    const int warp = tid >> 5, lane = tid & 31;
    const int wm = warp >> 2, wn = warp & 3;     // wm 0..1, wn 0..3
    const int gp = lane >> 2, tg = lane & 3;
    const int m0 = blockIdx.x * 64;

    // per-lane ldmatrix row address component
    const int lm = lane >> 3, lr = lane & 7;
    const uint32_t b_lane_off =
        (uint32_t)((wn * 64 + (lm >> 1) * 8 + lr) * ROWB_B + (lm & 1) * 16);

    va_s[tid] = va_w[tid];

    float acc[2][8][4];
#pragma unroll
    for (int a = 0; a < 2; a++)
#pragma unroll
        for (int b = 0; b < 8; b++)
#pragma unroll
            for (int c = 0; c < 4; c++) acc[a][b][c] = 0.f;

    // prologue: prefetch chunks 0,1
    issue_stage(sbase, 0, keys, m0, 0, tid);
    CP_COMMIT();
    issue_stage(sbase, 1, keys, m0, 32, tid);
    CP_COMMIT();

    for (int c = 0; c < 16; c++) {
        CP_WAIT1();
        __syncthreads();
        if (c + 2 < 16)
            issue_stage(sbase, (c + 2) % NSTG, keys, m0, (c + 2) * 32, tid);
        CP_COMMIT();

        const char* sA = smem + (c % NSTG) * STG_SZ;
        const uint32_t bbase = sbase + (c % NSTG) * STG_SZ + STG_A + b_lane_off;
#pragma unroll
        for (int ks = 0; ks < 32; ks += 16) {
            uint32_t af[2][4];
#pragma unroll
            for (int mt = 0; mt < 2; mt++) {
                int r0 = wm * 32 + mt * 16 + gp;
                const char* pa = sA + (ks + 2 * tg) * 4;
                float2 v0 = *(const float2*)(pa + r0 * ROWB_A);
                float2 v1 = *(const float2*)(pa + (r0 + 8) * ROWB_A);
                float2 v2 = *(const float2*)(pa + r0 * ROWB_A + 32);
                float2 v3 = *(const float2*)(pa + (r0 + 8) * ROWB_A + 32);
                af[mt][0] = pack_bf16x2(v0.x, v0.y);
                af[mt][1] = pack_bf16x2(v1.x, v1.y);
                af[mt][2] = pack_bf16x2(v2.x, v2.y);
                af[mt][3] = pack_bf16x2(v3.x, v3.y);
            }
            uint32_t bfr[8][2];
#pragma unroll
            for (int g = 0; g < 4; g++) {
                ldm_x4(bfr[2 * g][0], bfr[2 * g][1],
                       bfr[2 * g + 1][0], bfr[2 * g + 1][1],
                       bbase + (uint32_t)(g * 16 * ROWB_B + ks * 2));
            }
#pragma unroll
            for (int nt = 0; nt < 8; nt++) {
                mma_bf16(acc[0][nt], af[0], bfr[nt][0], bfr[nt][1]);
                mma_bf16(acc[1][nt], af[1], bfr[nt][0], bfr[nt][1]);
            }
        }
    }

    // load t2 into (now free) stage region
    __syncthreads();
#pragma unroll
    for (int i = 0; i < 16; i++) {
        int idx4 = tid + i * 256;                // 4096 float4s
        float4 v = *(const float4*)(g_t2 + idx4 * 4);
        int row = idx4 >> 6, col = (idx4 * 4) & 255;
        *(float4*)(t2s + row * T2STR + col) = v;
    }
    __syncthreads();

    // Epilogue: local row (0..63) == b.
    const float vb = va_b[0];
#pragma unroll
    for (int mt = 0; mt < 2; mt++) {
        int r0 = wm * 32 + mt * 16 + gp;
        int r1 = r0 + 8;
        const float* t2a = t2s + r0 * T2STR;
        const float* t2b = t2s + r1 * T2STR;
        float s0 = 0.f, s1 = 0.f;
#pragma unroll
        for (int nt = 0; nt < 8; nt++) {
            int n = wn * 64 + nt * 8 + 2 * tg;
            float v0 = va_s[n], v1 = va_s[n + 1];
            float x0 = acc[mt][nt][0] + t2a[n];
            float x1 = acc[mt][nt][1] + t2a[n + 1];
            float x2 = acc[mt][nt][2] + t2b[n];
            float x3 = acc[mt][nt][3] + t2b[n + 1];
            float h0, h1, h2, h3;
            asm("tanh.approx.f32 %0, %1;" : "=f"(h0) : "f"(x0));
            asm("tanh.approx.f32 %0, %1;" : "=f"(h1) : "f"(x1));
            asm("tanh.approx.f32 %0, %1;" : "=f"(h2) : "f"(x2));
            asm("tanh.approx.f32 %0, %1;" : "=f"(h3) : "f"(x3));
            s0 += h0 * v0 + h1 * v1;
            s1 += h2 * v0 + h3 * v1;
        }
        s0 += __shfl_xor_sync(0xffffffffu, s0, 1);
        s0 += __shfl_xor_sync(0xffffffffu, s0, 2);
        s1 += __shfl_xor_sync(0xffffffffu, s1, 1);
        s1 += __shfl_xor_sync(0xffffffffu, s1, 2);
        if (tg == 0) {
            red[wn * 64 + r0] = s0;
            red[wn * 64 + r1] = s1;
        }
    }
    __syncthreads();
    if (tid < 64) {
        g_scores[m0 + tid] =
            red[tid] + red[64 + tid] + red[128 + tid] + red[192 + tid] + vb;
    }
}

// ---------------------------------------------------------------------------
// Kernel C: softmax over p for each b; writes weights[p*64+b] to output.
// ---------------------------------------------------------------------------
__global__ __launch_bounds__(256) void softmax_kernel(float* __restrict__ out_w) {
    const int b = blockIdx.x;
    const int tid = threadIdx.x;
    float loc[16];
    float m = -1e30f;
#pragma unroll
    for (int i = 0; i < 16; i++) {
        loc[i] = g_scores[(size_t)(tid + i * 256) * NB + b];
        m = fmaxf(m, loc[i]);
    }
    __shared__ float sm[32];
    __shared__ float ss[32];
#pragma unroll
    for (int off = 16; off; off >>= 1) m = fmaxf(m, __shfl_xor_sync(0xffffffffu, m, off));
    if ((tid & 31) == 0) sm[tid >> 5] = m;
    __syncthreads();
    if (tid < 32) {
        float v = (tid < 8) ? sm[tid] : -1e30f;
#pragma unroll
        for (int off = 4; off; off >>= 1) v = fmaxf(v, __shfl_xor_sync(0xffffffffu, v, off));
        sm[tid] = v;
    }
    __syncthreads();
    m = sm[0];
    float sum = 0.f;
#pragma unroll
    for (int i = 0; i < 16; i++) { loc[i] = __expf(loc[i] - m); sum += loc[i]; }
#pragma unroll
    for (int off = 16; off; off >>= 1) sum += __shfl_xor_sync(0xffffffffu, sum, off);
    if ((tid & 31) == 0) ss[tid >> 5] = sum;
    __syncthreads();
    if (tid < 32) {
        float v = (tid < 8) ? ss[tid] : 0.f;
#pragma unroll
        for (int off = 4; off; off >>= 1) v += __shfl_xor_sync(0xffffffffu, v, off);
        ss[tid] = v;
    }
    __syncthreads();
    const float inv = 1.f / ss[0];
#pragma unroll
    for (int i = 0; i < 16; i++)
        out_w[(size_t)(tid + i * 256) * NB + b] = loc[i] * inv;
}

// ---------------------------------------------------------------------------
// Kernel D: context partials. grid = NSPLIT*NB CTAs, 128 threads (float4).
// ---------------------------------------------------------------------------
__global__ __launch_bounds__(128) void ctx_partial(
    const float* __restrict__ keys, const float* __restrict__ w) {
    const int b = blockIdx.x & (NB - 1);
    const int sp = blockIdx.x >> 6;
    const int c4 = threadIdx.x * 4;
    const int pc = NP / NSPLIT;  // 256
    const int p0 = sp * pc;
    float4 acc = make_float4(0.f, 0.f, 0.f, 0.f);
    for (int p = p0; p < p0 + pc; p += 4) {
        float w0 = __ldg(&w[(size_t)p * NB + b]);
        float w1 = __ldg(&w[(size_t)(p + 1) * NB + b]);
        float w2 = __ldg(&w[(size_t)(p + 2) * NB + b]);
        float w3 = __ldg(&w[(size_t)(p + 3) * NB + b]);
        float4 k0 = *(const float4*)(keys + ((size_t)p * NB + b) * NC + c4);
        float4 k1 = *(const float4*)(keys + ((size_t)(p + 1) * NB + b) * NC + c4);
        float4 k2 = *(const float4*)(keys + ((size_t)(p + 2) * NB + b) * NC + c4);
        float4 k3 = *(const float4*)(keys + ((size_t)(p + 3) * NB + b) * NC + c4);
        acc.x += w0 * k0.x + w1 * k1.x + w2 * k2.x + w3 * k3.x;
        acc.y += w0 * k0.y + w1 * k1.y + w2 * k2.y + w3 * k3.y;
        acc.z += w0 * k0.z + w1 * k1.z + w2 * k2.z + w3 * k3.z;
        acc.w += w0 * k0.w + w1 * k1.w + w2 * k2.w + w3 * k3.w;
    }
    *(float4*)(g_part + ((size_t)(sp * NB + b)) * NC + c4) = acc;
}

// ---------------------------------------------------------------------------
// Kernel E: combine partials -> context[b][c] in output.
// ---------------------------------------------------------------------------
__global__ __launch_bounds__(512) void ctx_combine(float* __restrict__ ctx) {
    const int b = blockIdx.x, c = threadIdx.x;
    float s = 0.f;
#pragma unroll
    for (int sp = 0; sp < NSPLIT; sp++)
        s += g_part[((size_t)(sp * NB + b)) * NC + c];
    ctx[b * NC + c] = s;
}

extern "C" void kernel_launch(void* const* d_in, const int* in_sizes, int n_in,
                              void* d_out, int out_size) {
    const float* keys    = (const float*)d_in[0];
    const float* queries = (const float*)d_in[1];
    const float* Wa_w    = (const float*)d_in[2];
    const float* Wa_b    = (const float*)d_in[3];
    const float* Ua_w    = (const float*)d_in[4];
    const float* Ua_b    = (const float*)d_in[5];
    const float* va_w    = (const float*)d_in[6];
    const float* va_b    = (const float*)d_in[7];

    float* out = (float*)d_out;
    float* ctx = out;                 // context: [1, B, C] = 32768 floats
    float* wts = out + NB * NC;       // weights: [P, B, 1] = 262144 floats

    cudaFuncSetAttribute(score_bf16, cudaFuncAttributeMaxDynamicSharedMemorySize,
                         SMEM_DYN);

    wa_cvt<<<NA * NC / 2 / 256, 256>>>(Wa_w);
    attn2_kernel<<<NB, NA>>>(queries, Ua_w, Ua_b, Wa_b);
    score_bf16<<<NP, 256, SMEM_DYN>>>(keys, va_w, va_b);
    softmax_kernel<<<NB, 256>>>(wts);
    ctx_partial<<<NSPLIT * NB, 128>>>(keys, wts);
    ctx_combine<<<NB, 512>>>(ctx);
}

// round 8
// speedup vs baseline: 1.8987x; 1.0041x over previous
#include <cuda_runtime.h>
#include <math.h>
#include <stdint.h>

#define NP 4096
#define NB 64
#define NC 512
#define NA 256
#define NSPLIT 16          // ctx CTAs per b; each CTA produces 2 partial slots

// Scratch (no device allocation allowed)
__device__ float g_t2[NB * NA];                 // attn2 + Wa_b + Ua_b folded
__device__ float g_scores[NP * NB];             // pre-softmax scores
__device__ float g_part[2 * NSPLIT * NB * NC];  // context partials (32 slots)
__device__ float g_msum[2 * NB];                // [b]=max, [64+b]=1/Z
__device__ uint32_t g_wab[NA * NC / 2];         // Wa_w as bf16x2 (256 KB)

// ---------------------------------------------------------------------------
// SMEM layout for score kernel (dynamic). A fp32 (160B rows), B bf16 (80B rows).
// M-tile = 64 rows -> 2 CTAs/SM.
// ---------------------------------------------------------------------------
#define ROWB_A 160
#define ROWB_B 80
#define STG_A (64 * ROWB_A)            // 10240
#define STG_B (256 * ROWB_B)           // 20480
#define STG_SZ (STG_A + STG_B)         // 30720
#define NSTG 3
#define OFF_VA (NSTG * STG_SZ)         // 92160
#define OFF_RED (OFF_VA + 256 * 4)     // 93184
#define SMEM_DYN (OFF_RED + 4 * 64 * 4 + 256)   // 94464
#define T2STR 260

__device__ __forceinline__ uint32_t smem_u32(const void* p) {
    uint32_t a;
    asm("{ .reg .u64 t; cvta.to.shared.u64 t, %1; cvt.u32.u64 %0, t; }" : "=r"(a) : "l"(p));
    return a;
}

__device__ __forceinline__ uint32_t pack_bf16x2(float lo, float hi) {
    uint32_t r;
    asm("cvt.rn.bf16x2.f32 %0, %1, %2;" : "=r"(r) : "f"(hi), "f"(lo));
    return r;
}

__device__ __forceinline__ void mma_bf16(float c[4], const uint32_t a[4],
                                         uint32_t b0, uint32_t b1) {
    asm volatile(
        "mma.sync.aligned.m16n8k16.row.col.f32.bf16.bf16.f32 "
        "{%0,%1,%2,%3}, {%4,%5,%6,%7}, {%8,%9}, {%0,%1,%2,%3};\n"
        : "+f"(c[0]), "+f"(c[1]), "+f"(c[2]), "+f"(c[3])
        : "r"(a[0]), "r"(a[1]), "r"(a[2]), "r"(a[3]), "r"(b0), "r"(b1));
}

__device__ __forceinline__ void ldm_x4(uint32_t& r0, uint32_t& r1,
                                       uint32_t& r2, uint32_t& r3, uint32_t addr) {
    asm volatile("ldmatrix.sync.aligned.m8n8.x4.shared.b16 {%0,%1,%2,%3}, [%4];"
                 : "=r"(r0), "=r"(r1), "=r"(r2), "=r"(r3) : "r"(addr));
}

__device__ __forceinline__ void cp16(uint32_t dst, const void* src) {
    asm volatile("cp.async.cg.shared.global [%0], [%1], 16;" :: "r"(dst), "l"(src));
}
#define CP_COMMIT() asm volatile("cp.async.commit_group;" ::: "memory")
#define CP_WAIT1()  asm volatile("cp.async.wait_group 1;" ::: "memory")

// ---------------------------------------------------------------------------
// Kernel P (merged prep): blocks 0..255 convert Wa_w -> bf16x2;
// blocks 256..319 compute t2[b][a] = Ua_w[a,:].queries[b,:] + Ua_b[a] + Wa_b[a]
// ---------------------------------------------------------------------------
__global__ __launch_bounds__(256) void prep_kernel(
    const float* __restrict__ Wa_w, const float* __restrict__ queries,
    const float* __restrict__ Ua_w, const float* __restrict__ Ua_b,
    const float* __restrict__ Wa_b) {
    __shared__ float qs[NC];
    if (blockIdx.x < 256) {
        int idx = blockIdx.x * 256 + threadIdx.x;   // 0..65535
        float2 v = *(const float2*)(Wa_w + idx * 2);
        g_wab[idx] = pack_bf16x2(v.x, v.y);
    } else {
        const int b = blockIdx.x - 256;
        for (int i = threadIdx.x; i < NC; i += 256) qs[i] = queries[b * NC + i];
        __syncthreads();
        const int a = threadIdx.x;
        const float* ua = Ua_w + (size_t)a * NC;
        float s = 0.f;
#pragma unroll 8
        for (int h = 0; h < NC; h++) s += ua[h] * qs[h];
        g_t2[b * NA + a] = s + Ua_b[a] + Wa_b[a];
    }
}

// ---------------------------------------------------------------------------
// Kernel B: score GEMM. A fp32->pack at frag; B bf16 via ldmatrix.
// CTA: M=64 (one pixel, all b), N=256, K=512 in 16 chunks of 32. 256 threads,
// 8 warps = 2(m) x 4(n), warp tile 32x64. cp.async 3-stage pipeline, 2 CTAs/SM.
// ---------------------------------------------------------------------------
__device__ __forceinline__ void issue_stage(uint32_t sbase, int s,
                                            const float* __restrict__ keys,
                                            int m0, int k0, int tid) {
    uint32_t aB = sbase + s * STG_SZ;
    uint32_t bB = aB + STG_A;
#pragma unroll
    for (int j = 0; j < 2; j++) {
        int idx = tid + j * 256;
        int row = idx >> 3, seg = idx & 7;
        cp16(aB + row * ROWB_A + seg * 16,
             keys + (size_t)(m0 + row) * NC + k0 + seg * 4);
    }
    const char* wab = (const char*)g_wab;
#pragma unroll
    for (int j = 0; j < 4; j++) {
        int idx = tid + j * 256;
        int row = idx >> 2, seg = idx & 3;
        cp16(bB + row * ROWB_B + seg * 16,
             wab + (size_t)row * (NC * 2) + k0 * 2 + seg * 16);
    }
}

__global__ __launch_bounds__(256, 2) void score_bf16(
    const float* __restrict__ keys,
    const float* __restrict__ va_w, const float* __restrict__ va_b) {
    extern __shared__ char smem[];
    const uint32_t sbase = smem_u32(smem);
    float* t2s = (float*)smem;                   // valid AFTER main loop only
    float* va_s = (float*)(smem + OFF_VA);
    float* red = (float*)(smem + OFF_RED);

    const int tid = threadIdx.x;
    const int warp = tid >> 5, lane = tid & 31;
    const int wm = warp >> 2, wn = warp & 3;
    const int gp = lane >> 2, tg = lane & 3;
    const int m0 = blockIdx.x * 64;

    const int lm = lane >> 3, lr = lane & 7;
    const uint32_t b_lane_off =
        (uint32_t)((wn * 64 + (lm >> 1) * 8 + lr) * ROWB_B + (lm & 1) * 16);

    va_s[tid] = va_w[tid];

    float acc[2][8][4];
#pragma unroll
    for (int a = 0; a < 2; a++)
#pragma unroll
        for (int b = 0; b < 8; b++)
#pragma unroll
            for (int c = 0; c < 4; c++) acc[a][b][c] = 0.f;

    issue_stage(sbase, 0, keys, m0, 0, tid);
    CP_COMMIT();
    issue_stage(sbase, 1, keys, m0, 32, tid);
    CP_COMMIT();

    for (int c = 0; c < 16; c++) {
        CP_WAIT1();
        __syncthreads();
        if (c + 2 < 16)
            issue_stage(sbase, (c + 2) % NSTG, keys, m0, (c + 2) * 32, tid);
        CP_COMMIT();

        const char* sA = smem + (c % NSTG) * STG_SZ;
        const uint32_t bbase = sbase + (c % NSTG) * STG_SZ + STG_A + b_lane_off;
#pragma unroll
        for (int ks = 0; ks < 32; ks += 16) {
            uint32_t af[2][4];
#pragma unroll
            for (int mt = 0; mt < 2; mt++) {
                int r0 = wm * 32 + mt * 16 + gp;
                const char* pa = sA + (ks + 2 * tg) * 4;
                float2 v0 = *(const float2*)(pa + r0 * ROWB_A);
                float2 v1 = *(const float2*)(pa + (r0 + 8) * ROWB_A);
                float2 v2 = *(const float2*)(pa + r0 * ROWB_A + 32);
                float2 v3 = *(const float2*)(pa + (r0 + 8) * ROWB_A + 32);
                af[mt][0] = pack_bf16x2(v0.x, v0.y);
                af[mt][1] = pack_bf16x2(v1.x, v1.y);
                af[mt][2] = pack_bf16x2(v2.x, v2.y);
                af[mt][3] = pack_bf16x2(v3.x, v3.y);
            }
            uint32_t bfr[8][2];
#pragma unroll
            for (int g = 0; g < 4; g++) {
                ldm_x4(bfr[2 * g][0], bfr[2 * g][1],
                       bfr[2 * g + 1][0], bfr[2 * g + 1][1],
                       bbase + (uint32_t)(g * 16 * ROWB_B + ks * 2));
            }
#pragma unroll
            for (int nt = 0; nt < 8; nt++) {
                mma_bf16(acc[0][nt], af[0], bfr[nt][0], bfr[nt][1]);
                mma_bf16(acc[1][nt], af[1], bfr[nt][0], bfr[nt][1]);
            }
        }
    }

    __syncthreads();
#pragma unroll
    for (int i = 0; i < 16; i++) {
        int idx4 = tid + i * 256;
        float4 v = *(const float4*)(g_t2 + idx4 * 4);
        int row = idx4 >> 6, col = (idx4 * 4) & 255;
        *(float4*)(t2s + row * T2STR + col) = v;
    }
    __syncthreads();

    const float vb = va_b[0];
#pragma unroll
    for (int mt = 0; mt < 2; mt++) {
        int r0 = wm * 32 + mt * 16 + gp;
        int r1 = r0 + 8;
        const float* t2a = t2s + r0 * T2STR;
        const float* t2b = t2s + r1 * T2STR;
        float s0 = 0.f, s1 = 0.f;
#pragma unroll
        for (int nt = 0; nt < 8; nt++) {
            int n = wn * 64 + nt * 8 + 2 * tg;
            float v0 = va_s[n], v1 = va_s[n + 1];
            float x0 = acc[mt][nt][0] + t2a[n];
            float x1 = acc[mt][nt][1] + t2a[n + 1];
            float x2 = acc[mt][nt][2] + t2b[n];
            float x3 = acc[mt][nt][3] + t2b[n + 1];
            float h0, h1, h2, h3;
            asm("tanh.approx.f32 %0, %1;" : "=f"(h0) : "f"(x0));
            asm("tanh.approx.f32 %0, %1;" : "=f"(h1) : "f"(x1));
            asm("tanh.approx.f32 %0, %1;" : "=f"(h2) : "f"(x2));
            asm("tanh.approx.f32 %0, %1;" : "=f"(h3) : "f"(x3));
            s0 += h0 * v0 + h1 * v1;
            s1 += h2 * v0 + h3 * v1;
        }
        s0 += __shfl_xor_sync(0xffffffffu, s0, 1);
        s0 += __shfl_xor_sync(0xffffffffu, s0, 2);
        s1 += __shfl_xor_sync(0xffffffffu, s1, 1);
        s1 += __shfl_xor_sync(0xffffffffu, s1, 2);
        if (tg == 0) {
            red[wn * 64 + r0] = s0;
            red[wn * 64 + r1] = s1;
        }
    }
    __syncthreads();
    if (tid < 64) {
        g_scores[m0 + tid] =
            red[tid] + red[64 + tid] + red[128 + tid] + red[192 + tid] + vb;
    }
}

// ---------------------------------------------------------------------------
// Kernel C: per-b softmax stats only: g_msum[b]=max, g_msum[64+b]=1/Z.
// Same reduction order as the previous softmax kernel (bit-identical Z).
// ---------------------------------------------------------------------------
__global__ __launch_bounds__(256) void softmax_reduce() {
    const int b = blockIdx.x;
    const int tid = threadIdx.x;
    float loc[16];
    float m = -1e30f;
#pragma unroll
    for (int i = 0; i < 16; i++) {
        loc[i] = g_scores[(size_t)(tid + i * 256) * NB + b];
        m = fmaxf(m, loc[i]);
    }
    __shared__ float sm[32];
    __shared__ float ss[32];
#pragma unroll
    for (int off = 16; off; off >>= 1) m = fmaxf(m, __shfl_xor_sync(0xffffffffu, m, off));
    if ((tid & 31) == 0) sm[tid >> 5] = m;
    __syncthreads();
    if (tid < 32) {
        float v = (tid < 8) ? sm[tid] : -1e30f;
#pragma unroll
        for (int off = 4; off; off >>= 1) v = fmaxf(v, __shfl_xor_sync(0xffffffffu, v, off));
        sm[tid] = v;
    }
    __syncthreads();
    m = sm[0];
    float sum = 0.f;
#pragma unroll
    for (int i = 0; i < 16; i++) { sum += __expf(loc[i] - m); }
#pragma unroll
    for (int off = 16; off; off >>= 1) sum += __shfl_xor_sync(0xffffffffu, sum, off);
    if ((tid & 31) == 0) ss[tid >> 5] = sum;
    __syncthreads();
    if (tid < 32) {
        float v = (tid < 8) ? ss[tid] : 0.f;
#pragma unroll
        for (int off = 4; off; off >>= 1) v += __shfl_xor_sync(0xffffffffu, v, off);
        ss[tid] = v;
    }
    __syncthreads();
    if (tid == 0) {
        g_msum[b] = m;
        g_msum[NB + b] = 1.f / ss[0];
    }
}

// ---------------------------------------------------------------------------
// Kernel D (fused): computes w = exp(s-m)*inv inline, writes weights output,
// and accumulates context partials. grid = NSPLIT*NB CTAs, 256 threads
// (2 p-lanes x 128 c-threads). Each CTA writes 2 partial slots.
// ---------------------------------------------------------------------------
__global__ __launch_bounds__(256) void ctx_partial(
    const float* __restrict__ keys, float* __restrict__ out_w) {
    const int b = blockIdx.x & (NB - 1);
    const int sp = blockIdx.x >> 6;              // 0..NSPLIT-1
    const int h = threadIdx.x >> 7;              // p-lane 0/1
    const int ct = threadIdx.x & 127;
    const int c4 = ct * 4;
    const float m = g_msum[b];
    const float inv = g_msum[NB + b];
    const int p0 = sp * (NP / NSPLIT);           // 256 pixels per CTA
    float4 acc = make_float4(0.f, 0.f, 0.f, 0.f);
    for (int i = 0; i < 32; i++) {
        int pb = p0 + i * 8 + h;                 // lane h covers pb, pb+2, pb+4, pb+6
        float w0 = __expf(g_scores[(size_t)pb * NB + b] - m) * inv;
        float w1 = __expf(g_scores[(size_t)(pb + 2) * NB + b] - m) * inv;
        float w2 = __expf(g_scores[(size_t)(pb + 4) * NB + b] - m) * inv;
        float w3 = __expf(g_scores[(size_t)(pb + 6) * NB + b] - m) * inv;
        if (ct == 0) {
            out_w[(size_t)pb * NB + b] = w0;
            out_w[(size_t)(pb + 2) * NB + b] = w1;
            out_w[(size_t)(pb + 4) * NB + b] = w2;
            out_w[(size_t)(pb + 6) * NB + b] = w3;
        }
        float4 k0 = *(const float4*)(keys + ((size_t)pb * NB + b) * NC + c4);
        float4 k1 = *(const float4*)(keys + ((size_t)(pb + 2) * NB + b) * NC + c4);
        float4 k2 = *(const float4*)(keys + ((size_t)(pb + 4) * NB + b) * NC + c4);
        float4 k3 = *(const float4*)(keys + ((size_t)(pb + 6) * NB + b) * NC + c4);
        acc.x += w0 * k0.x + w1 * k1.x + w2 * k2.x + w3 * k3.x;
        acc.y += w0 * k0.y + w1 * k1.y + w2 * k2.y + w3 * k3.y;
        acc.z += w0 * k0.z + w1 * k1.z + w2 * k2.z + w3 * k3.z;
        acc.w += w0 * k0.w + w1 * k1.w + w2 * k2.w + w3 * k3.w;
    }
    *(float4*)(g_part + ((size_t)((sp * 2 + h) * NB + b)) * NC + c4) = acc;
}

// ---------------------------------------------------------------------------
// Kernel E: combine 32 partials -> context[b][c] in output.
// ---------------------------------------------------------------------------
__global__ __launch_bounds__(512) void ctx_combine(float* __restrict__ ctx) {
    const int b = blockIdx.x, c = threadIdx.x;
    float s = 0.f;
#pragma unroll
    for (int sp = 0; sp < 2 * NSPLIT; sp++)
        s += g_part[((size_t)(sp * NB + b)) * NC + c];
    ctx[b * NC + c] = s;
}

extern "C" void kernel_launch(void* const* d_in, const int* in_sizes, int n_in,
                              void* d_out, int out_size) {
    const float* keys    = (const float*)d_in[0];
    const float* queries = (const float*)d_in[1];
    const float* Wa_w    = (const float*)d_in[2];
    const float* Wa_b    = (const float*)d_in[3];
    const float* Ua_w    = (const float*)d_in[4];
    const float* Ua_b    = (const float*)d_in[5];
    const float* va_w    = (const float*)d_in[6];
    const float* va_b    = (const float*)d_in[7];

    float* out = (float*)d_out;
    float* ctx = out;                 // context: [1, B, C] = 32768 floats
    float* wts = out + NB * NC;       // weights: [P, B, 1] = 262144 floats

    cudaFuncSetAttribute(score_bf16, cudaFuncAttributeMaxDynamicSharedMemorySize,
                         SMEM_DYN);

    prep_kernel<<<320, 256>>>(Wa_w, queries, Ua_w, Ua_b, Wa_b);
    score_bf16<<<NP, 256, SMEM_DYN>>>(keys, va_w, va_b);
    softmax_reduce<<<NB, 256>>>();
    ctx_partial<<<NSPLIT * NB, 256>>>(keys, wts);
    ctx_combine<<<NB, 512>>>(ctx);
}

// round 11
// speedup vs baseline: 1.9920x; 1.0491x over previous
#include <cuda_runtime.h>
#include <math.h>
#include <stdint.h>

#define NP 4096
#define NB 64
#define NC 512
#define NA 256
#define NSPLIT 16          // ctx CTAs per b; each CTA produces 2 partial slots

// Scratch (no device allocation allowed)
__device__ float g_t2[NB * NA];                 // attn2 + Wa_b + Ua_b folded
__device__ float g_scores[NP * NB];             // pre-softmax scores
__device__ float g_part[2 * NSPLIT * NB * NC];  // context partials (32 slots)
__device__ float g_msum[2 * NB];                // [b]=max, [64+b]=1/Z
__device__ uint32_t g_wab[NA * NC / 2];         // Wa_w as bf16x2 (256 KB)

// ---------------------------------------------------------------------------
// SMEM layout for score kernel. BOTH operands bf16 in smem.
//   A: 64 rows x 80B (32 bf16 + 16B pad) -> ldmatrix, 16B-aligned rows
//   B: 256 rows x 80B                    -> ldmatrix
// ---------------------------------------------------------------------------
#define ROWB_A 80
#define ROWB_B 80
#define STG_A (64 * ROWB_A)            // 5120
#define STG_B (256 * ROWB_B)           // 20480
#define STG_SZ (STG_A + STG_B)         // 25600
#define NSTG 3
#define OFF_VA (NSTG * STG_SZ)         // 76800
#define OFF_RED (OFF_VA + 256 * 4)     // 77824
#define SMEM_DYN (OFF_RED + 4 * 64 * 4 + 256)   // 79104
#define T2STR 260                      // t2s reuses stage region after loop

__device__ __forceinline__ uint32_t smem_u32(const void* p) {
    uint32_t a;
    asm("{ .reg .u64 t; cvta.to.shared.u64 t, %1; cvt.u32.u64 %0, t; }" : "=r"(a) : "l"(p));
    return a;
}

__device__ __forceinline__ uint32_t pack_bf16x2(float lo, float hi) {
    uint32_t r;
    asm("cvt.rn.bf16x2.f32 %0, %1, %2;" : "=r"(r) : "f"(hi), "f"(lo));
    return r;
}

__device__ __forceinline__ void mma_bf16(float c[4], const uint32_t a[4],
                                         uint32_t b0, uint32_t b1) {
    asm volatile(
        "mma.sync.aligned.m16n8k16.row.col.f32.bf16.bf16.f32 "
        "{%0,%1,%2,%3}, {%4,%5,%6,%7}, {%8,%9}, {%0,%1,%2,%3};\n"
        : "+f"(c[0]), "+f"(c[1]), "+f"(c[2]), "+f"(c[3])
        : "r"(a[0]), "r"(a[1]), "r"(a[2]), "r"(a[3]), "r"(b0), "r"(b1));
}

__device__ __forceinline__ void ldm_x4(uint32_t& r0, uint32_t& r1,
                                       uint32_t& r2, uint32_t& r3, uint32_t addr) {
    asm volatile("ldmatrix.sync.aligned.m8n8.x4.shared.b16 {%0,%1,%2,%3}, [%4];"
                 : "=r"(r0), "=r"(r1), "=r"(r2), "=r"(r3) : "r"(addr));
}

__device__ __forceinline__ void cp16(uint32_t dst, const void* src) {
    asm volatile("cp.async.cg.shared.global [%0], [%1], 16;" :: "r"(dst), "l"(src));
}
#define CP_COMMIT() asm volatile("cp.async.commit_group;" ::: "memory")
#define CP_WAIT1()  asm volatile("cp.async.wait_group 1;" ::: "memory")

// ---------------------------------------------------------------------------
// Kernel P (merged prep): blocks 0..255 convert Wa_w -> bf16x2;
// blocks 256..319 compute t2[b][a] = Ua_w[a,:].queries[b,:] + Ua_b[a] + Wa_b[a]
// ---------------------------------------------------------------------------
__global__ __launch_bounds__(256) void prep_kernel(
    const float* __restrict__ Wa_w, const float* __restrict__ queries,
    const float* __restrict__ Ua_w, const float* __restrict__ Ua_b,
    const float* __restrict__ Wa_b) {
    __shared__ float qs[NC];
    if (blockIdx.x < 256) {
        int idx = blockIdx.x * 256 + threadIdx.x;   // 0..65535
        float2 v = *(const float2*)(Wa_w + idx * 2);
        g_wab[idx] = pack_bf16x2(v.x, v.y);
    } else {
        const int b = blockIdx.x - 256;
        for (int i = threadIdx.x; i < NC; i += 256) qs[i] = queries[b * NC + i];
        __syncthreads();
        const int a = threadIdx.x;
        const float* ua = Ua_w + (size_t)a * NC;
        float s = 0.f;
#pragma unroll 8
        for (int h = 0; h < NC; h++) s += ua[h] * qs[h];
        g_t2[b * NA + a] = s + Ua_b[a] + Wa_b[a];
    }
}

// ---------------------------------------------------------------------------
// Kernel B: score GEMM. BOTH operands bf16 via ldmatrix.
// A: LDG fp32 -> cvt.rn bf16 -> STS, register-pipelined at distance 2.
// B: cp.async from pre-converted g_wab.
// CTA: M=64, N=256, K=512 in 16 chunks of 32. 256 threads, 8 warps 2x4,
// warp tile 32x64, 3 stages, 2 CTAs/SM.
// ---------------------------------------------------------------------------
__device__ __forceinline__ void issue_B(uint32_t sbase, int s, int k0, int tid) {
    uint32_t bB = sbase + s * STG_SZ + STG_A;
    const char* wab = (const char*)g_wab;
#pragma unroll
    for (int j = 0; j < 4; j++) {
        int idx = tid + j * 256;
        int row = idx >> 2, seg = idx & 3;
        cp16(bB + row * ROWB_B + seg * 16,
             wab + (size_t)row * (NC * 2) + k0 * 2 + seg * 16);
    }
}

__global__ __launch_bounds__(256, 2) void score_bf16(
    const float* __restrict__ keys,
    const float* __restrict__ va_w, const float* __restrict__ va_b) {
    extern __shared__ char smem[];
    const uint32_t sbase = smem_u32(smem);
    float* t2s = (float*)smem;                   // valid AFTER main loop only
    float* va_s = (float*)(smem + OFF_VA);
    float* red = (float*)(smem + OFF_RED);

    const int tid = threadIdx.x;
    const int warp = tid >> 5, lane = tid & 31;
    const int wm = warp >> 2, wn = warp & 3;
    const int gp = lane >> 2, tg = lane & 3;
    const int m0 = blockIdx.x * 64;

    // A-fragment ldmatrix lane mapping (matrices: r0-7/k0-7, r8-15/k0-7,
    // r0-7/k8-15, r8-15/k8-15):
    const int a_lmr = (lane & 7) + ((lane >> 3) & 1) * 8;
    const int a_lmk = ((lane >> 4) & 1) * 16;
    const uint32_t a_lane_off = (uint32_t)(a_lmr * ROWB_A + a_lmk);

    // B-fragment ldmatrix lane mapping (matrices: n0-7/k0-7, n0-7/k8-15,
    // n8-15/k0-7, n8-15/k8-15) — the R6-R8 proven mapping:
    const int lm = lane >> 3, lr = lane & 7;
    const uint32_t b_lane_off =
        (uint32_t)((wn * 64 + (lm >> 1) * 8 + lr) * ROWB_B + (lm & 1) * 16);

    // A loader mapping: thread t -> row=t>>2, 8 floats at (t&3)*8
    const int arow = tid >> 2, aseg = (tid & 3) * 8;
    const float* keyrow = keys + (size_t)(m0 + arow) * NC + aseg;
    const uint32_t a_sts_off = (uint32_t)(arow * ROWB_A + (tid & 3) * 16);

    va_s[tid] = va_w[tid];

    float acc[2][8][4];
#pragma unroll
    for (int a = 0; a < 2; a++)
#pragma unroll
        for (int b = 0; b < 8; b++)
#pragma unroll
            for (int c = 0; c < 4; c++) acc[a][b][c] = 0.f;

    float4 ra0, ra1;

    // prologue: A chunk0 -> stage0 (regs->smem), A chunk1 -> regs,
    //           B chunks 0,1 via cp.async
    ra0 = *(const float4*)(keyrow);
    ra1 = *(const float4*)(keyrow + 4);
    {
        uint4 w;
        w.x = pack_bf16x2(ra0.x, ra0.y); w.y = pack_bf16x2(ra0.z, ra0.w);
        w.z = pack_bf16x2(ra1.x, ra1.y); w.w = pack_bf16x2(ra1.z, ra1.w);
        *(uint4*)(smem + a_sts_off) = w;         // stage 0
    }
    ra0 = *(const float4*)(keyrow + 32);
    ra1 = *(const float4*)(keyrow + 36);
    issue_B(sbase, 0, 0, tid);
    CP_COMMIT();
    issue_B(sbase, 1, 32, tid);
    CP_COMMIT();
    __syncthreads();

    for (int c = 0; c < 16; c++) {
        CP_WAIT1();
        __syncthreads();
        // STS A for chunk c+1 (regs loaded last iteration)
        if (c + 1 < 16) {
            uint4 w;
            w.x = pack_bf16x2(ra0.x, ra0.y); w.y = pack_bf16x2(ra0.z, ra0.w);
            w.z = pack_bf16x2(ra1.x, ra1.y); w.w = pack_bf16x2(ra1.z, ra1.w);
            *(uint4*)(smem + ((c + 1) % NSTG) * STG_SZ + a_sts_off) = w;
        }
        // LDG A for chunk c+2; issue B for chunk c+2
        if (c + 2 < 16) {
            const int k0 = (c + 2) * 32;
            ra0 = *(const float4*)(keyrow + k0);
            ra1 = *(const float4*)(keyrow + k0 + 4);
            issue_B(sbase, (c + 2) % NSTG, k0, tid);
        }
        CP_COMMIT();

        const uint32_t stg = sbase + (c % NSTG) * STG_SZ;
        const uint32_t abase = stg + a_lane_off + (uint32_t)(wm * 32 * ROWB_A);
        const uint32_t bbase = stg + STG_A + b_lane_off;
#pragma unroll
        for (int ks = 0; ks < 32; ks += 16) {
            uint32_t af[2][4];
            ldm_x4(af[0][0], af[0][1], af[0][2], af[0][3],
                   abase + (uint32_t)(ks * 2));
            ldm_x4(af[1][0], af[1][1], af[1][2], af[1][3],
                   abase + (uint32_t)(16 * ROWB_A + ks * 2));
            uint32_t bfr[8][2];
#pragma unroll
            for (int g = 0; g < 4; g++) {
                ldm_x4(bfr[2 * g][0], bfr[2 * g][1],
                       bfr[2 * g + 1][0], bfr[2 * g + 1][1],
                       bbase + (uint32_t)(g * 16 * ROWB_B + ks * 2));
            }
#pragma unroll
            for (int nt = 0; nt < 8; nt++) {
                mma_bf16(acc[0][nt], af[0], bfr[nt][0], bfr[nt][1]);
                mma_bf16(acc[1][nt], af[1], bfr[nt][0], bfr[nt][1]);
            }
        }
    }

    // load t2 into (now free) stage region
    __syncthreads();
#pragma unroll
    for (int i = 0; i < 16; i++) {
        int idx4 = tid + i * 256;
        float4 v = *(const float4*)(g_t2 + idx4 * 4);
        int row = idx4 >> 6, col = (idx4 * 4) & 255;
        *(float4*)(t2s + row * T2STR + col) = v;
    }
    __syncthreads();

    // Epilogue: local row (0..63) == b.
    const float vb = va_b[0];
#pragma unroll
    for (int mt = 0; mt < 2; mt++) {
        int r0 = wm * 32 + mt * 16 + gp;
        int r1 = r0 + 8;
        const float* t2a = t2s + r0 * T2STR;
        const float* t2b = t2s + r1 * T2STR;
        float s0 = 0.f, s1 = 0.f;
#pragma unroll
        for (int nt = 0; nt < 8; nt++) {
            int n = wn * 64 + nt * 8 + 2 * tg;
            float v0 = va_s[n], v1 = va_s[n + 1];
            float x0 = acc[mt][nt][0] + t2a[n];
            float x1 = acc[mt][nt][1] + t2a[n + 1];
            float x2 = acc[mt][nt][2] + t2b[n];
            float x3 = acc[mt][nt][3] + t2b[n + 1];
            float h0, h1, h2, h3;
            asm("tanh.approx.f32 %0, %1;" : "=f"(h0) : "f"(x0));
            asm("tanh.approx.f32 %0, %1;" : "=f"(h1) : "f"(x1));
            asm("tanh.approx.f32 %0, %1;" : "=f"(h2) : "f"(x2));
            asm("tanh.approx.f32 %0, %1;" : "=f"(h3) : "f"(x3));
            s0 += h0 * v0 + h1 * v1;
            s1 += h2 * v0 + h3 * v1;
        }
        s0 += __shfl_xor_sync(0xffffffffu, s0, 1);
        s0 += __shfl_xor_sync(0xffffffffu, s0, 2);
        s1 += __shfl_xor_sync(0xffffffffu, s1, 1);
        s1 += __shfl_xor_sync(0xffffffffu, s1, 2);
        if (tg == 0) {
            red[wn * 64 + r0] = s0;
            red[wn * 64 + r1] = s1;
        }
    }
    __syncthreads();
    if (tid < 64) {
        g_scores[m0 + tid] =
            red[tid] + red[64 + tid] + red[128 + tid] + red[192 + tid] + vb;
    }
}

// ---------------------------------------------------------------------------
// Kernel C: per-b softmax stats only: g_msum[b]=max, g_msum[64+b]=1/Z.
// ---------------------------------------------------------------------------
__global__ __launch_bounds__(256) void softmax_reduce() {
    const int b = blockIdx.x;
    const int tid = threadIdx.x;
    float loc[16];
    float m = -1e30f;
#pragma unroll
    for (int i = 0; i < 16; i++) {
        loc[i] = g_scores[(size_t)(tid + i * 256) * NB + b];
        m = fmaxf(m, loc[i]);
    }
    __shared__ float sm[32];
    __shared__ float ss[32];
#pragma unroll
    for (int off = 16; off; off >>= 1) m = fmaxf(m, __shfl_xor_sync(0xffffffffu, m, off));
    if ((tid & 31) == 0) sm[tid >> 5] = m;
    __syncthreads();
    if (tid < 32) {
        float v = (tid < 8) ? sm[tid] : -1e30f;
#pragma unroll
        for (int off = 4; off; off >>= 1) v = fmaxf(v, __shfl_xor_sync(0xffffffffu, v, off));
        sm[tid] = v;
    }
    __syncthreads();
    m = sm[0];
    float sum = 0.f;
#pragma unroll
    for (int i = 0; i < 16; i++) { sum += __expf(loc[i] - m); }
#pragma unroll
    for (int off = 16; off; off >>= 1) sum += __shfl_xor_sync(0xffffffffu, sum, off);
    if ((tid & 31) == 0) ss[tid >> 5] = sum;
    __syncthreads();
    if (tid < 32) {
        float v = (tid < 8) ? ss[tid] : 0.f;
#pragma unroll
        for (int off = 4; off; off >>= 1) v += __shfl_xor_sync(0xffffffffu, v, off);
        ss[tid] = v;
    }
    __syncthreads();
    if (tid == 0) {
        g_msum[b] = m;
        g_msum[NB + b] = 1.f / ss[0];
    }
}

// ---------------------------------------------------------------------------
// Kernel D (fused): w = exp(s-m)*inv inline, writes weights, accumulates
// context partials. grid = NSPLIT*NB CTAs, 256 threads (2 p-lanes x 128 c).
// ---------------------------------------------------------------------------
__global__ __launch_bounds__(256) void ctx_partial(
    const float* __restrict__ keys, float* __restrict__ out_w) {
    const int b = blockIdx.x & (NB - 1);
    const int sp = blockIdx.x >> 6;
    const int h = threadIdx.x >> 7;
    const int ct = threadIdx.x & 127;
    const int c4 = ct * 4;
    const float m = g_msum[b];
    const float inv = g_msum[NB + b];
    const int p0 = sp * (NP / NSPLIT);
    float4 acc = make_float4(0.f, 0.f, 0.f, 0.f);
    for (int i = 0; i < 32; i++) {
        int pb = p0 + i * 8 + h;
        float w0 = __expf(g_scores[(size_t)pb * NB + b] - m) * inv;
        float w1 = __expf(g_scores[(size_t)(pb + 2) * NB + b] - m) * inv;
        float w2 = __expf(g_scores[(size_t)(pb + 4) * NB + b] - m) * inv;
        float w3 = __expf(g_scores[(size_t)(pb + 6) * NB + b] - m) * inv;
        if (ct == 0) {
            out_w[(size_t)pb * NB + b] = w0;
            out_w[(size_t)(pb + 2) * NB + b] = w1;
            out_w[(size_t)(pb + 4) * NB + b] = w2;
            out_w[(size_t)(pb + 6) * NB + b] = w3;
        }
        float4 k0 = *(const float4*)(keys + ((size_t)pb * NB + b) * NC + c4);
        float4 k1 = *(const float4*)(keys + ((size_t)(pb + 2) * NB + b) * NC + c4);
        float4 k2 = *(const float4*)(keys + ((size_t)(pb + 4) * NB + b) * NC + c4);
        float4 k3 = *(const float4*)(keys + ((size_t)(pb + 6) * NB + b) * NC + c4);
        acc.x += w0 * k0.x + w1 * k1.x + w2 * k2.x + w3 * k3.x;
        acc.y += w0 * k0.y + w1 * k1.y + w2 * k2.y + w3 * k3.y;
        acc.z += w0 * k0.z + w1 * k1.z + w2 * k2.z + w3 * k3.z;
        acc.w += w0 * k0.w + w1 * k1.w + w2 * k2.w + w3 * k3.w;
    }
    *(float4*)(g_part + ((size_t)((sp * 2 + h) * NB + b)) * NC + c4) = acc;
}

// ---------------------------------------------------------------------------
// Kernel E: combine 32 partials -> context[b][c] in output.
// ---------------------------------------------------------------------------
__global__ __launch_bounds__(512) void ctx_combine(float* __restrict__ ctx) {
    const int b = blockIdx.x, c = threadIdx.x;
    float s = 0.f;
#pragma unroll
    for (int sp = 0; sp < 2 * NSPLIT; sp++)
        s += g_part[((size_t)(sp * NB + b)) * NC + c];
    ctx[b * NC + c] = s;
}

extern "C" void kernel_launch(void* const* d_in, const int* in_sizes, int n_in,
                              void* d_out, int out_size) {
    const float* keys    = (const float*)d_in[0];
    const float* queries = (const float*)d_in[1];
    const float* Wa_w    = (const float*)d_in[2];
    const float* Wa_b    = (const float*)d_in[3];
    const float* Ua_w    = (const float*)d_in[4];
    const float* Ua_b    = (const float*)d_in[5];
    const float* va_w    = (const float*)d_in[6];
    const float* va_b    = (const float*)d_in[7];

    float* out = (float*)d_out;
    float* ctx = out;                 // context: [1, B, C] = 32768 floats
    float* wts = out + NB * NC;       // weights: [P, B, 1] = 262144 floats

    cudaFuncSetAttribute(score_bf16, cudaFuncAttributeMaxDynamicSharedMemorySize,
                         SMEM_DYN);

    prep_kernel<<<320, 256>>>(Wa_w, queries, Ua_w, Ua_b, Wa_b);
    score_bf16<<<NP, 256, SMEM_DYN>>>(keys, va_w, va_b);
    softmax_reduce<<<NB, 256>>>();
    ctx_partial<<<NSPLIT * NB, 256>>>(keys, wts);
    ctx_combine<<<NB, 512>>>(ctx);
}